// round 2
// baseline (speedup 1.0000x reference)
#include <cuda_runtime.h>
#include <cstdint>

#define NN 50000
#define EE 640000
#define GG 256
#define HH 128
#define NODE_IN 32
#define EDGE_IN 16
#define EXT_IN 8
#define BN_EPS 1e-5f

// ---------------- device scratch (static; no allocations) ----------------
__device__ __align__(16) float g_h[(size_t)NN * HH];
__device__ __align__(16) float g_e[(size_t)EE * HH];
__device__ __align__(16) float g_z[(size_t)NN * HH];
__device__ __align__(16) float g_t[(size_t)NN * HH];
__device__ __align__(16) float g_pool[GG * HH];
__device__ int    g_cnt[GG];
__device__ int    g_rowptr[NN + 1];
__device__ int    g_fill[NN];
__device__ int2   g_edge[EE];          // (src, eid) grouped by dst
__device__ double g_bnsum[HH];
__device__ double g_bnsq[HH];
__device__ __align__(16) float g_bnscale[HH];
__device__ __align__(16) float g_bnshift[HH];

// ---------------- packed f32x2 helpers ----------------
__device__ __forceinline__ unsigned long long pk2(float lo, float hi) {
    unsigned long long r;
    asm("mov.b64 %0, {%1, %2};" : "=l"(r) : "f"(lo), "f"(hi));
    return r;
}
__device__ __forceinline__ void upk2(unsigned long long v, float& lo, float& hi) {
    asm("mov.b64 {%0, %1}, %2;" : "=f"(lo), "=f"(hi) : "l"(v));
}
__device__ __forceinline__ unsigned long long ffma2(unsigned long long a,
                                                    unsigned long long b,
                                                    unsigned long long c) {
    unsigned long long d;
    asm("fma.rn.f32x2 %0, %1, %2, %3;" : "=l"(d) : "l"(a), "l"(b), "l"(c));
    return d;
}

// ---- GEMM core: 128 threads, C tile 64x128 = A(64x128) @ W(128x128), 8x8 micro ----
__device__ __forceinline__ void gemm_128(const float* As, const float* Ws,
                                         unsigned long long acc[8][4], int r0, int c0) {
    for (int k4 = 0; k4 < HH; k4 += 4) {
        float4 a[8];
#pragma unroll
        for (int i = 0; i < 8; i++)
            a[i] = *(const float4*)(As + (r0 + i) * HH + k4);
#pragma unroll
        for (int kk = 0; kk < 4; kk++) {
            const float4 w0 = *(const float4*)(Ws + (k4 + kk) * HH + c0);
            const float4 w1 = *(const float4*)(Ws + (k4 + kk) * HH + c0 + 4);
            unsigned long long wp0 = pk2(w0.x, w0.y);
            unsigned long long wp1 = pk2(w0.z, w0.w);
            unsigned long long wp2 = pk2(w1.x, w1.y);
            unsigned long long wp3 = pk2(w1.z, w1.w);
#pragma unroll
            for (int i = 0; i < 8; i++) {
                float av = (kk == 0) ? a[i].x : (kk == 1) ? a[i].y : (kk == 2) ? a[i].z : a[i].w;
                unsigned long long av2 = pk2(av, av);
                acc[i][0] = ffma2(av2, wp0, acc[i][0]);
                acc[i][1] = ffma2(av2, wp1, acc[i][1]);
                acc[i][2] = ffma2(av2, wp2, acc[i][2]);
                acc[i][3] = ffma2(av2, wp3, acc[i][3]);
            }
        }
    }
}

__device__ __forceinline__ void gemm_epilogue(unsigned long long acc[8][4],
                                              const float* __restrict__ bias,
                                              float* __restrict__ C, int M,
                                              int rowBase, int r0, int c0, bool do_relu) {
    float4 b0 = *(const float4*)(bias + c0);
    float4 b1 = *(const float4*)(bias + c0 + 4);
#pragma unroll
    for (int i = 0; i < 8; i++) {
        int gr = rowBase + r0 + i;
        if (gr < M) {
            float o0, o1, o2, o3, o4, o5, o6, o7;
            upk2(acc[i][0], o0, o1);
            upk2(acc[i][1], o2, o3);
            upk2(acc[i][2], o4, o5);
            upk2(acc[i][3], o6, o7);
            o0 += b0.x; o1 += b0.y; o2 += b0.z; o3 += b0.w;
            o4 += b1.x; o5 += b1.y; o6 += b1.z; o7 += b1.w;
            if (do_relu) {
                o0 = fmaxf(o0, 0.f); o1 = fmaxf(o1, 0.f); o2 = fmaxf(o2, 0.f); o3 = fmaxf(o3, 0.f);
                o4 = fmaxf(o4, 0.f); o5 = fmaxf(o5, 0.f); o6 = fmaxf(o6, 0.f); o7 = fmaxf(o7, 0.f);
            }
            *(float4*)(C + (size_t)gr * HH + c0)     = make_float4(o0, o1, o2, o3);
            *(float4*)(C + (size_t)gr * HH + c0 + 4) = make_float4(o4, o5, o6, o7);
        }
    }
}

// ---------------- generic [M,128]@[128,128]+b (optional relu) ----------------
__global__ void __launch_bounds__(128) k_gemm(const float* __restrict__ A,
                                              const float* __restrict__ W,
                                              const float* __restrict__ bias,
                                              float* __restrict__ C, int M, int do_relu) {
    extern __shared__ float smem[];
    float* As = smem;             // 64*128
    float* Ws = smem + 64 * HH;   // 128*128
    int tid = threadIdx.x;
    int rowBase = blockIdx.x * 64;

    const float4* W4 = (const float4*)W;
    float4* Ws4 = (float4*)Ws;
#pragma unroll
    for (int i = 0; i < 32; i++) Ws4[tid + 128 * i] = W4[tid + 128 * i];

    const float4* A4 = (const float4*)A;
    float4* As4 = (float4*)As;
#pragma unroll
    for (int i = 0; i < 16; i++) {
        int idx = tid + 128 * i;          // 2048 float4
        int r = idx >> 5;
        int gr = rowBase + r;
        float4 v = make_float4(0.f, 0.f, 0.f, 0.f);
        if (gr < M) v = A4[(size_t)gr * 32 + (idx & 31)];
        As4[idx] = v;
    }
    __syncthreads();

    int c0 = (tid & 15) * 8, r0 = (tid >> 4) * 8;
    unsigned long long acc[8][4];
#pragma unroll
    for (int i = 0; i < 8; i++)
#pragma unroll
        for (int j = 0; j < 4; j++) acc[i][j] = 0ull;

    gemm_128(As, Ws, acc, r0, c0);
    gemm_epilogue(acc, bias, C, M, rowBase, r0, c0, do_relu != 0);
}

// -------- fused edge encoder: g_e = relu(ea@W1+b1)@W2+b2, 64 edges/block --------
__global__ void __launch_bounds__(128) k_edge_enc(const float* __restrict__ ea,
                                                  const float* __restrict__ w1,
                                                  const float* __restrict__ b1,
                                                  const float* __restrict__ w2,
                                                  const float* __restrict__ b2) {
    extern __shared__ float smem[];
    float* Hs  = smem;                      // 64*128
    float* Ws  = Hs + 64 * HH;              // 128*128
    float* Ea  = Ws + HH * HH;              // 64*16
    float* W1s = Ea + 64 * EDGE_IN;         // 16*128
    float* B1s = W1s + EDGE_IN * HH;        // 128
    int tid = threadIdx.x;
    int e0 = blockIdx.x * 64;

    const float4* W24 = (const float4*)w2;
    float4* Ws4 = (float4*)Ws;
#pragma unroll
    for (int i = 0; i < 32; i++) Ws4[tid + 128 * i] = W24[tid + 128 * i];

    const float4* Eg4 = (const float4*)ea;
    float4* Ea4 = (float4*)Ea;
#pragma unroll
    for (int i = 0; i < 2; i++) {
        int idx = tid + 128 * i;            // 256 float4 = 64 rows * 4
        Ea4[idx] = Eg4[(size_t)e0 * 4 + idx];
    }
    const float4* W14 = (const float4*)w1;
    float4* W1s4 = (float4*)W1s;
#pragma unroll
    for (int i = 0; i < 4; i++) W1s4[tid + 128 * i] = W14[tid + 128 * i];
    B1s[tid] = b1[tid];
    __syncthreads();

    // phase 1: hidden = relu(ea@W1+b1); thread = one output column
    float w1r[16];
#pragma unroll
    for (int k = 0; k < 16; k++) w1r[k] = W1s[k * HH + tid];
    float bb = B1s[tid];
    for (int r = 0; r < 64; r++) {
        const float4* er = (const float4*)(Ea + r * EDGE_IN);
        float4 x0 = er[0], x1 = er[1], x2 = er[2], x3 = er[3];
        float s = bb;
        s = fmaf(x0.x, w1r[0], s);  s = fmaf(x0.y, w1r[1], s);
        s = fmaf(x0.z, w1r[2], s);  s = fmaf(x0.w, w1r[3], s);
        s = fmaf(x1.x, w1r[4], s);  s = fmaf(x1.y, w1r[5], s);
        s = fmaf(x1.z, w1r[6], s);  s = fmaf(x1.w, w1r[7], s);
        s = fmaf(x2.x, w1r[8], s);  s = fmaf(x2.y, w1r[9], s);
        s = fmaf(x2.z, w1r[10], s); s = fmaf(x2.w, w1r[11], s);
        s = fmaf(x3.x, w1r[12], s); s = fmaf(x3.y, w1r[13], s);
        s = fmaf(x3.z, w1r[14], s); s = fmaf(x3.w, w1r[15], s);
        Hs[r * HH + tid] = fmaxf(s, 0.f);
    }
    __syncthreads();

    // phase 2: e = hidden @ W2 + b2
    int c0 = (tid & 15) * 8, r0 = (tid >> 4) * 8;
    unsigned long long acc[8][4];
#pragma unroll
    for (int i = 0; i < 8; i++)
#pragma unroll
        for (int j = 0; j < 4; j++) acc[i][j] = 0ull;
    gemm_128(Hs, Ws, acc, r0, c0);
    gemm_epilogue(acc, b2, g_e, EE, e0, r0, c0, false);
}

// ---------------- node encoder: g_h = x @ node_w + node_b ----------------
__global__ void __launch_bounds__(128) k_node_enc(const float* __restrict__ x,
                                                  const float* __restrict__ w,
                                                  const float* __restrict__ b) {
    __shared__ float Xs[64 * NODE_IN];
    __shared__ float Wn[NODE_IN * HH];
    int tid = threadIdx.x;
    int rowBase = blockIdx.x * 64;

    const float4* W4 = (const float4*)w;
    float4* Wn4 = (float4*)Wn;
#pragma unroll
    for (int i = 0; i < 8; i++) Wn4[tid + 128 * i] = W4[tid + 128 * i];

    const float4* X4 = (const float4*)x;
    float4* Xs4 = (float4*)Xs;
#pragma unroll
    for (int i = 0; i < 4; i++) {
        int idx = tid + 128 * i;            // 512 float4
        int r = idx >> 3;
        int gr = rowBase + r;
        float4 v = make_float4(0.f, 0.f, 0.f, 0.f);
        if (gr < NN) v = X4[(size_t)gr * 8 + (idx & 7)];
        Xs4[idx] = v;
    }
    __syncthreads();

    float wr[32];
#pragma unroll
    for (int k = 0; k < 32; k++) wr[k] = Wn[k * HH + tid];
    float bv = b[tid];
    for (int r = 0; r < 64; r++) {
        int gr = rowBase + r;
        if (gr >= NN) break;
        const float4* xr = (const float4*)(Xs + r * NODE_IN);
        float s = bv;
#pragma unroll
        for (int q = 0; q < 8; q++) {
            float4 xv = xr[q];
            s = fmaf(xv.x, wr[4 * q + 0], s);
            s = fmaf(xv.y, wr[4 * q + 1], s);
            s = fmaf(xv.z, wr[4 * q + 2], s);
            s = fmaf(xv.w, wr[4 * q + 3], s);
        }
        g_h[(size_t)gr * HH + tid] = s;
    }
}

// ---------------- CSR build ----------------
__global__ void k_zero() {
    int i = blockIdx.x * blockDim.x + threadIdx.x;
    if (i < NN) g_fill[i] = 0;
    if (i < GG * HH) g_pool[i] = 0.f;
    if (i < GG) g_cnt[i] = 0;
}
__global__ void k_degree(const int* __restrict__ dst) {
    int i = blockIdx.x * blockDim.x + threadIdx.x;
    if (i < EE) atomicAdd(&g_fill[dst[i]], 1);
}
__global__ void k_scan() {   // single block, 1024 threads: exclusive scan
    __shared__ int sdata[1024];
    __shared__ int carry;
    int tid = threadIdx.x;
    if (tid == 0) carry = 0;
    __syncthreads();
    for (int base = 0; base < NN; base += 1024) {
        int v = (base + tid < NN) ? g_fill[base + tid] : 0;
        sdata[tid] = v;
        __syncthreads();
        for (int off = 1; off < 1024; off <<= 1) {
            int t = (tid >= off) ? sdata[tid - off] : 0;
            __syncthreads();
            sdata[tid] += t;
            __syncthreads();
        }
        int cb = carry;
        if (base + tid < NN) {
            g_rowptr[base + tid] = cb + sdata[tid] - v;
            g_fill[base + tid] = 0;     // reset for fill pass
        }
        __syncthreads();
        if (tid == 0) carry = cb + sdata[1023];
        __syncthreads();
    }
    if (tid == 0) g_rowptr[NN] = carry;
}
__global__ void k_fillcsr(const int* __restrict__ ei) {
    int i = blockIdx.x * blockDim.x + threadIdx.x;
    if (i < EE) {
        int s = ei[i];
        int d = ei[EE + i];
        int p = atomicAdd(&g_fill[d], 1);
        g_edge[g_rowptr[d] + p] = make_int2(s, i);
    }
}

// -------- aggregation: g_z = h + sum_{e:dst=v} relu(h[src]+e); warp=node --------
__global__ void __launch_bounds__(256) k_aggregate() {
    int gw = (blockIdx.x * 256 + threadIdx.x) >> 5;
    int lane = threadIdx.x & 31;
    if (gw >= NN) return;
    int beg = g_rowptr[gw], end = g_rowptr[gw + 1];
    const float4* h4 = (const float4*)g_h;
    const float4* e4 = (const float4*)g_e;
    float4 acc = make_float4(0.f, 0.f, 0.f, 0.f);
    for (int j = beg; j < end; j++) {
        int2 se = g_edge[j];
        float4 hv = h4[(size_t)se.x * 32 + lane];
        float4 ev = e4[(size_t)se.y * 32 + lane];
        acc.x += fmaxf(hv.x + ev.x, 0.f);
        acc.y += fmaxf(hv.y + ev.y, 0.f);
        acc.z += fmaxf(hv.z + ev.z, 0.f);
        acc.w += fmaxf(hv.w + ev.w, 0.f);
    }
    float4 hv = h4[(size_t)gw * 32 + lane];
    acc.x += hv.x; acc.y += hv.y; acc.z += hv.z; acc.w += hv.w;
    ((float4*)g_z)[(size_t)gw * 32 + lane] = acc;
}

// ---------------- batchnorm ----------------
__global__ void k_bnzero() {
    int c = threadIdx.x;
    g_bnsum[c] = 0.0;
    g_bnsq[c] = 0.0;
}
__global__ void __launch_bounds__(128) k_bnstats() {
    int c = threadIdx.x;
    int r0 = blockIdx.x * 512;
    int re = min(r0 + 512, NN);
    double s = 0.0, s2 = 0.0;
    for (int r = r0; r < re; r++) {
        float v = g_z[(size_t)r * HH + c];
        s += (double)v;
        s2 += (double)v * (double)v;
    }
    atomicAdd(&g_bnsum[c], s);
    atomicAdd(&g_bnsq[c], s2);
}
__global__ void k_bnfinal(const float* __restrict__ gamma, const float* __restrict__ beta) {
    int c = threadIdx.x;
    double mean = g_bnsum[c] / (double)NN;
    double var = g_bnsq[c] / (double)NN - mean * mean;
    double inv = rsqrt(var + (double)BN_EPS);
    float sc = (float)((double)gamma[c] * inv);
    g_bnscale[c] = sc;
    g_bnshift[c] = (float)((double)beta[c] - mean * (double)sc);
}
__global__ void k_bnapply() {
    int idx = blockIdx.x * blockDim.x + threadIdx.x;   // float4 index
    if (idx >= NN * 32) return;
    int c4 = idx & 31;
    float4 z = ((const float4*)g_z)[idx];
    float4 sc = ((const float4*)g_bnscale)[c4];
    float4 sh = ((const float4*)g_bnshift)[c4];
    float4 h;
    h.x = fmaxf(fmaf(z.x, sc.x, sh.x), 0.f);
    h.y = fmaxf(fmaf(z.y, sc.y, sh.y), 0.f);
    h.z = fmaxf(fmaf(z.z, sc.z, sh.z), 0.f);
    h.w = fmaxf(fmaf(z.w, sc.w, sh.w), 0.f);
    ((float4*)g_h)[idx] = h;
}

// ---------------- pooling ----------------
__global__ void k_cnt(const int* __restrict__ batch) {
    int i = blockIdx.x * blockDim.x + threadIdx.x;
    if (i < NN) atomicAdd(&g_cnt[batch[i]], 1);
}
__global__ void __launch_bounds__(128) k_pool(const int* __restrict__ batch) {
    __shared__ int sb[256];
    int c = threadIdx.x;
    int r0 = blockIdx.x * 256;
    for (int i = c; i < 256; i += 128) {
        int r = r0 + i;
        sb[i] = (r < NN) ? batch[r] : -1;
    }
    __syncthreads();
    int rend = min(256, NN - r0);
    if (rend <= 0) return;
    int cur = sb[0];
    float acc = 0.f;
    for (int i = 0; i < rend; i++) {
        int b = sb[i];
        if (b != cur) {
            atomicAdd(&g_pool[cur * HH + c], acc);
            acc = 0.f;
            cur = b;
        }
        acc += g_h[(size_t)(r0 + i) * HH + c];
    }
    atomicAdd(&g_pool[cur * HH + c], acc);
}

// -------- per-graph head: ext MLP + concat + regressor; block = graph --------
__global__ void __launch_bounds__(128) k_final(const float* __restrict__ ext,
                                               const float* __restrict__ ew1,
                                               const float* __restrict__ eb1,
                                               const float* __restrict__ ew2,
                                               const float* __restrict__ eb2,
                                               const float* __restrict__ rw1,
                                               const float* __restrict__ rb1,
                                               const float* __restrict__ rw2,
                                               const float* __restrict__ rb2,
                                               float* __restrict__ out) {
    int g = blockIdx.x, c = threadIdx.x;
    __shared__ float shid[HH];
    __shared__ float comb[2 * HH];
    __shared__ float red[HH];
    float xin[EXT_IN];
#pragma unroll
    for (int k = 0; k < EXT_IN; k++) xin[k] = ext[g * EXT_IN + k];
    float hval = eb1[c];
#pragma unroll
    for (int k = 0; k < EXT_IN; k++) hval = fmaf(xin[k], ew1[k * HH + c], hval);
    shid[c] = fmaxf(hval, 0.f);
    __syncthreads();
    float eo = eb2[c];
    for (int k = 0; k < HH; k++) eo = fmaf(shid[k], ew2[k * HH + c], eo);
    float cnt = fmaxf((float)g_cnt[g], 1.f);
    comb[c] = g_pool[g * HH + c] / cnt;
    comb[HH + c] = eo;
    __syncthreads();
    float rh = rb1[c];
    for (int k = 0; k < 2 * HH; k++) rh = fmaf(comb[k], rw1[k * HH + c], rh);
    rh = fmaxf(rh, 0.f);
    red[c] = rh * rw2[c];
    __syncthreads();
    for (int s = 64; s > 0; s >>= 1) {
        if (c < s) red[c] += red[c + s];
        __syncthreads();
    }
    if (c == 0) out[g] = red[0] + rb2[0];
}

// ---------------- host launcher ----------------
#define SM_GEMM ((64 * HH + HH * HH) * 4)
#define SM_EDGE ((64 * HH + HH * HH + 64 * EDGE_IN + EDGE_IN * HH + HH) * 4)

extern "C" void kernel_launch(void* const* d_in, const int* in_sizes, int n_in,
                              void* d_out, int out_size) {
    const float* x         = (const float*)d_in[0];
    const float* edge_attr = (const float*)d_in[1];
    const float* externals = (const float*)d_in[2];
    const float* node_w    = (const float*)d_in[3];
    const float* node_b    = (const float*)d_in[4];
    const float* ee_w1     = (const float*)d_in[5];
    const float* ee_b1     = (const float*)d_in[6];
    const float* ee_w2     = (const float*)d_in[7];
    const float* ee_b2     = (const float*)d_in[8];
    const float* conv_w1   = (const float*)d_in[9];
    const float* conv_b1   = (const float*)d_in[10];
    const float* conv_w2   = (const float*)d_in[11];
    const float* conv_b2   = (const float*)d_in[12];
    const float* bn_gamma  = (const float*)d_in[13];
    const float* bn_beta   = (const float*)d_in[14];
    const float* ext_w1    = (const float*)d_in[15];
    const float* ext_b1    = (const float*)d_in[16];
    const float* ext_w2    = (const float*)d_in[17];
    const float* ext_b2    = (const float*)d_in[18];
    const float* reg_w1    = (const float*)d_in[19];
    const float* reg_b1    = (const float*)d_in[20];
    const float* reg_w2    = (const float*)d_in[21];
    const float* reg_b2    = (const float*)d_in[22];
    const int* edge_index  = (const int*)d_in[23];
    const int* batch       = (const int*)d_in[24];
    float* out = (float*)d_out;

    static bool attr_done = false;
    if (!attr_done) {
        cudaFuncSetAttribute(k_gemm, cudaFuncAttributeMaxDynamicSharedMemorySize, SM_GEMM);
        cudaFuncSetAttribute(k_edge_enc, cudaFuncAttributeMaxDynamicSharedMemorySize, SM_EDGE);
        attr_done = true;
    }

    float *p_z, *p_t;
    cudaGetSymbolAddress((void**)&p_z, g_z);
    cudaGetSymbolAddress((void**)&p_t, g_t);

    // CSR build (edge_index invariant across layers)
    k_zero<<<(NN + 255) / 256, 256>>>();
    k_degree<<<(EE + 255) / 256, 256>>>(edge_index + EE);
    k_scan<<<1, 1024>>>();
    k_fillcsr<<<(EE + 255) / 256, 256>>>(edge_index);

    // encoders
    k_node_enc<<<(NN + 63) / 64, 128>>>(x, node_w, node_b);
    k_edge_enc<<<EE / 64, 128, SM_EDGE>>>(edge_attr, ee_w1, ee_b1, ee_w2, ee_b2);

    // 3x (GINEConv + MLP + BN + relu)
    for (int l = 0; l < 3; l++) {
        k_aggregate<<<(NN * 32 + 255) / 256, 256>>>();
        k_gemm<<<(NN + 63) / 64, 128, SM_GEMM>>>(p_z, conv_w1 + (size_t)l * HH * HH,
                                                 conv_b1 + (size_t)l * HH, p_t, NN, 1);
        k_gemm<<<(NN + 63) / 64, 128, SM_GEMM>>>(p_t, conv_w2 + (size_t)l * HH * HH,
                                                 conv_b2 + (size_t)l * HH, p_z, NN, 0);
        k_bnzero<<<1, 128>>>();
        k_bnstats<<<(NN + 511) / 512, 128>>>();
        k_bnfinal<<<1, 128>>>(bn_gamma + (size_t)l * HH, bn_beta + (size_t)l * HH);
        k_bnapply<<<(NN * 32 + 255) / 256, 256>>>();
    }

    // pooling + head
    k_cnt<<<(NN + 255) / 256, 256>>>(batch);
    k_pool<<<(NN + 255) / 256, 128>>>(batch);
    k_final<<<GG, 128>>>(externals, ext_w1, ext_b1, ext_w2, ext_b2,
                         reg_w1, reg_b1, reg_w2, reg_b2, out);
}

// round 4
// speedup vs baseline: 1.2296x; 1.2296x over previous
#include <cuda_runtime.h>
#include <cuda_bf16.h>
#include <cstdint>

#define NN 50000
#define EE 640000
#define GG 256
#define HH 128
#define NODE_IN 32
#define EDGE_IN 16
#define EXT_IN 8
#define BN_EPS 1e-5f
#define SA 136            // padded bf16 row stride (elements): 272B rows, conflict-free
#define SMEM_TC 147456

// ---------------- device scratch (static; no allocations) ----------------
__device__ __align__(16) float g_h[(size_t)NN * HH];
__device__ __align__(16) float g_e[(size_t)EE * HH];   // dst-sorted edge features
__device__ __align__(16) float g_z[(size_t)NN * HH];
__device__ __align__(16) float g_t[(size_t)NN * HH];
__device__ __align__(16) float g_pool[GG * HH];
__device__ int    g_cnt[GG];
__device__ int    g_rowptr[NN + 1];
__device__ int    g_fill[NN];
__device__ int    g_src[EE];    // src node per CSR slot
__device__ int    g_pos[EE];    // eid -> CSR slot
__device__ double g_bnsum[HH];
__device__ double g_bnsq[HH];
__device__ __align__(16) float g_bnscale[HH];
__device__ __align__(16) float g_bnshift[HH];
// pre-split weights: [m][hi|lo][n][k] bf16, transposed to n-major
__device__ __align__(16) __nv_bfloat16 g_wsp[7 * 2 * HH * HH];

// ---------------- bf16 split helpers ----------------
__device__ __forceinline__ void split2(float x, float y, unsigned& hi, unsigned& lo) {
    __nv_bfloat162 h = __floats2bfloat162_rn(x, y);
    float hx = __bfloat162float(h.x), hy = __bfloat162float(h.y);
    __nv_bfloat162 l = __floats2bfloat162_rn(x - hx, y - hy);
    hi = reinterpret_cast<unsigned&>(h);
    lo = reinterpret_cast<unsigned&>(l);
}

// ---------------- mma.sync bf16 ----------------
__device__ __forceinline__ void mma_bf16(float c[4], unsigned a0, unsigned a1,
                                         unsigned a2, unsigned a3,
                                         unsigned b0, unsigned b1) {
    asm("mma.sync.aligned.m16n8k16.row.col.f32.bf16.bf16.f32 "
        "{%0,%1,%2,%3}, {%4,%5,%6,%7}, {%8,%9}, {%0,%1,%2,%3};"
        : "+f"(c[0]), "+f"(c[1]), "+f"(c[2]), "+f"(c[3])
        : "r"(a0), "r"(a1), "r"(a2), "r"(a3), "r"(b0), "r"(b1));
}

// C[16 rows x 128 cols] per warp = A(16x128 split bf16, smem) @ W(128x128 split bf16, smem [n][k])
// 3-term split: AhBh + AlBh + AhBl
__device__ __forceinline__ void gemm_tc(const __nv_bfloat16* Ah, const __nv_bfloat16* Al,
                                        const __nv_bfloat16* Wh, const __nv_bfloat16* Wl,
                                        float c[16][4], int rb, int lane) {
    int g = lane >> 2, t2 = (lane & 3) * 2;
    const __nv_bfloat16* arh0 = Ah + (rb + g) * SA + t2;
    const __nv_bfloat16* arh1 = Ah + (rb + g + 8) * SA + t2;
    const __nv_bfloat16* arl0 = Al + (rb + g) * SA + t2;
    const __nv_bfloat16* arl1 = Al + (rb + g + 8) * SA + t2;
    for (int ks = 0; ks < 8; ks++) {
        int k0 = ks * 16;
        unsigned ah0 = *(const unsigned*)(arh0 + k0);
        unsigned ah1 = *(const unsigned*)(arh1 + k0);
        unsigned ah2 = *(const unsigned*)(arh0 + k0 + 8);
        unsigned ah3 = *(const unsigned*)(arh1 + k0 + 8);
        unsigned al0 = *(const unsigned*)(arl0 + k0);
        unsigned al1 = *(const unsigned*)(arl1 + k0);
        unsigned al2 = *(const unsigned*)(arl0 + k0 + 8);
        unsigned al3 = *(const unsigned*)(arl1 + k0 + 8);
#pragma unroll
        for (int nb = 0; nb < 16; nb++) {
            const __nv_bfloat16* wh = Wh + (nb * 8 + g) * SA + k0 + t2;
            const __nv_bfloat16* wl = Wl + (nb * 8 + g) * SA + k0 + t2;
            unsigned bh0 = *(const unsigned*)(wh);
            unsigned bh1 = *(const unsigned*)(wh + 8);
            unsigned bl0 = *(const unsigned*)(wl);
            unsigned bl1 = *(const unsigned*)(wl + 8);
            mma_bf16(c[nb], ah0, ah1, ah2, ah3, bh0, bh1);
            mma_bf16(c[nb], al0, al1, al2, al3, bh0, bh1);
            mma_bf16(c[nb], ah0, ah1, ah2, ah3, bl0, bl1);
        }
    }
}

// copy one pre-split 128x128 bf16 matrix (n-major) into padded smem
__device__ __forceinline__ void copy_w(const __nv_bfloat16* __restrict__ src,
                                       __nv_bfloat16* dstH_base, int tid) {
    const uint4* s4 = (const uint4*)src;
    for (int i = tid; i < 2048; i += 256) {
        int n = i >> 4, ch = i & 15;
        *(uint4*)((char*)dstH_base + n * 272 + ch * 16) = s4[i];
    }
}

// ---------------- weight split (fp32 [k][n] -> bf16 hi/lo [n][k]) ----------------
__global__ void k_wsplit(const float* __restrict__ w, int m) {
    int idx = blockIdx.x * 256 + threadIdx.x;
    if (idx >= HH * HH) return;
    int k = idx >> 7, n = idx & 127;
    float a = w[idx];
    __nv_bfloat16 hi = __float2bfloat16(a);
    __nv_bfloat16 lo = __float2bfloat16(a - __bfloat162float(hi));
    size_t base = (size_t)m * 2 * HH * HH;
    g_wsp[base + n * HH + k] = hi;
    g_wsp[base + HH * HH + n * HH + k] = lo;
}

// ---------------- edge encoder: g_e[pos] = relu(ea@W1+b1)@W2+b2 ----------------
__global__ void __launch_bounds__(256) k_edge_tc(const float* __restrict__ ea,
                                                 const float* __restrict__ w1,
                                                 const float* __restrict__ b1,
                                                 const __nv_bfloat16* __restrict__ w2sp,
                                                 const float* __restrict__ b2) {
    extern __shared__ char smem[];
    float* Ea = (float*)smem;                                  // 128*16 f32
    __nv_bfloat16* Ah = (__nv_bfloat16*)(smem + 8192);
    __nv_bfloat16* Al = Ah + 128 * SA;
    __nv_bfloat16* Wh = Al + 128 * SA;
    __nv_bfloat16* Wl = Wh + 128 * SA;
    int tid = threadIdx.x, lane = tid & 31, wid = tid >> 5;
    int e0 = blockIdx.x * 128;

    const float4* ea4 = (const float4*)ea;
    float4* Ea4 = (float4*)Ea;
#pragma unroll
    for (int i = 0; i < 2; i++) Ea4[tid + 256 * i] = ea4[(size_t)e0 * 4 + tid + 256 * i];
    copy_w(w2sp, Wh, tid);
    copy_w(w2sp + HH * HH, Wl, tid);
    __syncthreads();

    // phase 1: hidden = relu(ea@W1+b1), split to bf16 hi/lo
    {
        int col = tid & 127, rh = tid >> 7;
        float w1r[16];
#pragma unroll
        for (int k = 0; k < 16; k++) w1r[k] = w1[k * HH + col];
        float bb = b1[col];
        for (int r = rh * 64; r < rh * 64 + 64; r++) {
            const float4* er = (const float4*)(Ea + r * EDGE_IN);
            float4 x0 = er[0], x1 = er[1], x2 = er[2], x3 = er[3];
            float s = bb;
            s = fmaf(x0.x, w1r[0], s);  s = fmaf(x0.y, w1r[1], s);
            s = fmaf(x0.z, w1r[2], s);  s = fmaf(x0.w, w1r[3], s);
            s = fmaf(x1.x, w1r[4], s);  s = fmaf(x1.y, w1r[5], s);
            s = fmaf(x1.z, w1r[6], s);  s = fmaf(x1.w, w1r[7], s);
            s = fmaf(x2.x, w1r[8], s);  s = fmaf(x2.y, w1r[9], s);
            s = fmaf(x2.z, w1r[10], s); s = fmaf(x2.w, w1r[11], s);
            s = fmaf(x3.x, w1r[12], s); s = fmaf(x3.y, w1r[13], s);
            s = fmaf(x3.z, w1r[14], s); s = fmaf(x3.w, w1r[15], s);
            s = fmaxf(s, 0.f);
            __nv_bfloat16 hi = __float2bfloat16(s);
            Ah[r * SA + col] = hi;
            Al[r * SA + col] = __float2bfloat16(s - __bfloat162float(hi));
        }
    }
    __syncthreads();

    float c[16][4];
#pragma unroll
    for (int i = 0; i < 16; i++)
#pragma unroll
        for (int j = 0; j < 4; j++) c[i][j] = 0.f;
    gemm_tc(Ah, Al, Wh, Wl, c, wid * 16, lane);

    int g = lane >> 2, t2 = (lane & 3) * 2;
    int row0 = wid * 16 + g, row1 = row0 + 8;
    int p0 = g_pos[e0 + row0], p1 = g_pos[e0 + row1];
#pragma unroll
    for (int nb = 0; nb < 16; nb++) {
        int col = nb * 8 + t2;
        float2 bb = *(const float2*)(b2 + col);
        *(float2*)(g_e + (size_t)p0 * HH + col) = make_float2(c[nb][0] + bb.x, c[nb][1] + bb.y);
        *(float2*)(g_e + (size_t)p1 * HH + col) = make_float2(c[nb][2] + bb.x, c[nb][3] + bb.y);
    }
}

// ---------------- fused conv MLP: z2 = (relu(A@W1+b1))@W2+b2, + BN partial stats ----------------
__global__ void __launch_bounds__(256) k_conv_tc(const float* __restrict__ A,
                                                 const __nv_bfloat16* __restrict__ w1sp,
                                                 const __nv_bfloat16* __restrict__ w2sp,
                                                 const float* __restrict__ b1,
                                                 const float* __restrict__ b2,
                                                 float* __restrict__ Cc, int M) {
    extern __shared__ char smem[];
    __nv_bfloat16* Ah = (__nv_bfloat16*)smem;
    __nv_bfloat16* Al = Ah + 128 * SA;
    __nv_bfloat16* Wh = Al + 128 * SA;
    __nv_bfloat16* Wl = Wh + 128 * SA;
    float* redS = (float*)(smem + 4 * 128 * SA * 2);           // [8][128]
    float* redQ = redS + 8 * 128;                              // [8][128]
    int tid = threadIdx.x, lane = tid & 31, wid = tid >> 5;
    int rowBase = blockIdx.x * 128;

    // load + split A tile
    const float4* A4 = (const float4*)A;
    for (int idx = tid; idx < 128 * 32; idx += 256) {
        int r = idx >> 5, q = idx & 31;
        int gr = rowBase + r;
        float4 v = make_float4(0.f, 0.f, 0.f, 0.f);
        if (gr < M) v = A4[(size_t)gr * 32 + q];
        unsigned h0, l0, h1, l1;
        split2(v.x, v.y, h0, l0);
        split2(v.z, v.w, h1, l1);
        *(unsigned*)(Ah + r * SA + q * 4) = h0;
        *(unsigned*)(Ah + r * SA + q * 4 + 2) = h1;
        *(unsigned*)(Al + r * SA + q * 4) = l0;
        *(unsigned*)(Al + r * SA + q * 4 + 2) = l1;
    }
    copy_w(w1sp, Wh, tid);
    copy_w(w1sp + HH * HH, Wl, tid);
    __syncthreads();

    float c[16][4];
#pragma unroll
    for (int i = 0; i < 16; i++)
#pragma unroll
        for (int j = 0; j < 4; j++) c[i][j] = 0.f;
    gemm_tc(Ah, Al, Wh, Wl, c, wid * 16, lane);

    int g = lane >> 2, t2 = (lane & 3) * 2;
    int rb = wid * 16;
    // hidden = relu(c + b1), split, write back over own rows of Ah/Al
#pragma unroll
    for (int nb = 0; nb < 16; nb++) {
        int col = nb * 8 + t2;
        float2 bb = *(const float2*)(b1 + col);
        float h00 = fmaxf(c[nb][0] + bb.x, 0.f);
        float h01 = fmaxf(c[nb][1] + bb.y, 0.f);
        float h10 = fmaxf(c[nb][2] + bb.x, 0.f);
        float h11 = fmaxf(c[nb][3] + bb.y, 0.f);
        unsigned hi, lo;
        split2(h00, h01, hi, lo);
        *(unsigned*)(Ah + (rb + g) * SA + col) = hi;
        *(unsigned*)(Al + (rb + g) * SA + col) = lo;
        split2(h10, h11, hi, lo);
        *(unsigned*)(Ah + (rb + g + 8) * SA + col) = hi;
        *(unsigned*)(Al + (rb + g + 8) * SA + col) = lo;
    }
    __syncthreads();               // all reads of W1 + writes of hidden done
    copy_w(w2sp, Wh, tid);
    copy_w(w2sp + HH * HH, Wl, tid);
    __syncthreads();

#pragma unroll
    for (int i = 0; i < 16; i++)
#pragma unroll
        for (int j = 0; j < 4; j++) c[i][j] = 0.f;
    gemm_tc(Ah, Al, Wh, Wl, c, rb, lane);

    // epilogue: z = c + b2 (no relu) -> global, plus BN column partial sums
    int r0g = rowBase + rb + g, r1g = r0g + 8;
    bool v0 = r0g < M, v1 = r1g < M;
#pragma unroll
    for (int nb = 0; nb < 16; nb++) {
        int col = nb * 8 + t2;
        float2 bb = *(const float2*)(b2 + col);
        float z00 = c[nb][0] + bb.x, z01 = c[nb][1] + bb.y;
        float z10 = c[nb][2] + bb.x, z11 = c[nb][3] + bb.y;
        if (v0) *(float2*)(Cc + (size_t)r0g * HH + col) = make_float2(z00, z01);
        if (v1) *(float2*)(Cc + (size_t)r1g * HH + col) = make_float2(z10, z11);
        float s0 = (v0 ? z00 : 0.f) + (v1 ? z10 : 0.f);
        float s1 = (v0 ? z01 : 0.f) + (v1 ? z11 : 0.f);
        float q0 = (v0 ? z00 * z00 : 0.f) + (v1 ? z10 * z10 : 0.f);
        float q1 = (v0 ? z01 * z01 : 0.f) + (v1 ? z11 * z11 : 0.f);
#pragma unroll
        for (int m = 4; m <= 16; m <<= 1) {
            s0 += __shfl_xor_sync(0xffffffffu, s0, m);
            s1 += __shfl_xor_sync(0xffffffffu, s1, m);
            q0 += __shfl_xor_sync(0xffffffffu, q0, m);
            q1 += __shfl_xor_sync(0xffffffffu, q1, m);
        }
        if (lane < 4) {
            redS[wid * 128 + col] = s0;
            redS[wid * 128 + col + 1] = s1;
            redQ[wid * 128 + col] = q0;
            redQ[wid * 128 + col + 1] = q1;
        }
    }
    __syncthreads();
    if (tid < 128) {
        float s = 0.f;
#pragma unroll
        for (int w = 0; w < 8; w++) s += redS[w * 128 + tid];
        atomicAdd(&g_bnsum[tid], (double)s);
    } else {
        int col = tid - 128;
        float s = 0.f;
#pragma unroll
        for (int w = 0; w < 8; w++) s += redQ[w * 128 + col];
        atomicAdd(&g_bnsq[col], (double)s);
    }
}

// ---------------- node encoder: g_h = x @ node_w + node_b ----------------
__global__ void __launch_bounds__(128) k_node_enc(const float* __restrict__ x,
                                                  const float* __restrict__ w,
                                                  const float* __restrict__ b) {
    __shared__ float Xs[64 * NODE_IN];
    __shared__ float Wn[NODE_IN * HH];
    int tid = threadIdx.x;
    int rowBase = blockIdx.x * 64;
    const float4* W4 = (const float4*)w;
    float4* Wn4 = (float4*)Wn;
#pragma unroll
    for (int i = 0; i < 8; i++) Wn4[tid + 128 * i] = W4[tid + 128 * i];
    const float4* X4 = (const float4*)x;
    float4* Xs4 = (float4*)Xs;
#pragma unroll
    for (int i = 0; i < 4; i++) {
        int idx = tid + 128 * i;
        int r = idx >> 3;
        int gr = rowBase + r;
        float4 v = make_float4(0.f, 0.f, 0.f, 0.f);
        if (gr < NN) v = X4[(size_t)gr * 8 + (idx & 7)];
        Xs4[idx] = v;
    }
    __syncthreads();
    float wr[32];
#pragma unroll
    for (int k = 0; k < 32; k++) wr[k] = Wn[k * HH + tid];
    float bv = b[tid];
    for (int r = 0; r < 64; r++) {
        int gr = rowBase + r;
        if (gr >= NN) break;
        const float4* xr = (const float4*)(Xs + r * NODE_IN);
        float s = bv;
#pragma unroll
        for (int q = 0; q < 8; q++) {
            float4 xv = xr[q];
            s = fmaf(xv.x, wr[4 * q + 0], s);
            s = fmaf(xv.y, wr[4 * q + 1], s);
            s = fmaf(xv.z, wr[4 * q + 2], s);
            s = fmaf(xv.w, wr[4 * q + 3], s);
        }
        g_h[(size_t)gr * HH + tid] = s;
    }
}

// ---------------- CSR build ----------------
__global__ void k_zero() {
    int i = blockIdx.x * blockDim.x + threadIdx.x;
    if (i < NN) g_fill[i] = 0;
    if (i < GG * HH) g_pool[i] = 0.f;
    if (i < GG) g_cnt[i] = 0;
}
__global__ void k_degree(const int* __restrict__ dst) {
    int i = blockIdx.x * blockDim.x + threadIdx.x;
    if (i < EE) atomicAdd(&g_fill[dst[i]], 1);
}
__global__ void k_scan() {
    __shared__ int sdata[1024];
    __shared__ int carry;
    int tid = threadIdx.x;
    if (tid == 0) carry = 0;
    __syncthreads();
    for (int base = 0; base < NN; base += 1024) {
        int v = (base + tid < NN) ? g_fill[base + tid] : 0;
        sdata[tid] = v;
        __syncthreads();
        for (int off = 1; off < 1024; off <<= 1) {
            int t = (tid >= off) ? sdata[tid - off] : 0;
            __syncthreads();
            sdata[tid] += t;
            __syncthreads();
        }
        int cb = carry;
        if (base + tid < NN) {
            g_rowptr[base + tid] = cb + sdata[tid] - v;
            g_fill[base + tid] = 0;
        }
        __syncthreads();
        if (tid == 0) carry = cb + sdata[1023];
        __syncthreads();
    }
    if (tid == 0) g_rowptr[NN] = carry;
}
__global__ void k_fillcsr(const int* __restrict__ ei) {
    int i = blockIdx.x * blockDim.x + threadIdx.x;
    if (i < EE) {
        int s = ei[i];
        int d = ei[EE + i];
        int p = atomicAdd(&g_fill[d], 1);
        int slot = g_rowptr[d] + p;
        g_src[slot] = s;
        g_pos[i] = slot;
    }
}

// ---- aggregation: out = h_self + sum relu(h[src]+e), h = bn?relu(z*sc+sh):z ----
__global__ void __launch_bounds__(256) k_aggregate(const float* __restrict__ in,
                                                   float* __restrict__ outp, int bnflag) {
    int gw = (blockIdx.x * 256 + threadIdx.x) >> 5;
    int lane = threadIdx.x & 31;
    if (gw >= NN) return;
    float4 sc = make_float4(1.f, 1.f, 1.f, 1.f);
    float4 sh = make_float4(0.f, 0.f, 0.f, 0.f);
    if (bnflag) {
        sc = ((const float4*)g_bnscale)[lane];
        sh = ((const float4*)g_bnshift)[lane];
    }
    int beg = g_rowptr[gw], end = g_rowptr[gw + 1];
    const float4* h4 = (const float4*)in;
    const float4* e4 = (const float4*)g_e;
    float4 acc = make_float4(0.f, 0.f, 0.f, 0.f);
    int j = beg;
    for (; j + 2 <= end; j += 2) {
        int s0 = g_src[j], s1 = g_src[j + 1];
        float4 e0 = e4[(size_t)j * 32 + lane];
        float4 e1 = e4[(size_t)(j + 1) * 32 + lane];
        float4 h0 = h4[(size_t)s0 * 32 + lane];
        float4 h1 = h4[(size_t)s1 * 32 + lane];
        h0.x = fmaf(h0.x, sc.x, sh.x); h0.y = fmaf(h0.y, sc.y, sh.y);
        h0.z = fmaf(h0.z, sc.z, sh.z); h0.w = fmaf(h0.w, sc.w, sh.w);
        h1.x = fmaf(h1.x, sc.x, sh.x); h1.y = fmaf(h1.y, sc.y, sh.y);
        h1.z = fmaf(h1.z, sc.z, sh.z); h1.w = fmaf(h1.w, sc.w, sh.w);
        if (bnflag) {
            h0.x = fmaxf(h0.x, 0.f); h0.y = fmaxf(h0.y, 0.f);
            h0.z = fmaxf(h0.z, 0.f); h0.w = fmaxf(h0.w, 0.f);
            h1.x = fmaxf(h1.x, 0.f); h1.y = fmaxf(h1.y, 0.f);
            h1.z = fmaxf(h1.z, 0.f); h1.w = fmaxf(h1.w, 0.f);
        }
        acc.x += fmaxf(h0.x + e0.x, 0.f) + fmaxf(h1.x + e1.x, 0.f);
        acc.y += fmaxf(h0.y + e0.y, 0.f) + fmaxf(h1.y + e1.y, 0.f);
        acc.z += fmaxf(h0.z + e0.z, 0.f) + fmaxf(h1.z + e1.z, 0.f);
        acc.w += fmaxf(h0.w + e0.w, 0.f) + fmaxf(h1.w + e1.w, 0.f);
    }
    if (j < end) {
        int s0 = g_src[j];
        float4 e0 = e4[(size_t)j * 32 + lane];
        float4 h0 = h4[(size_t)s0 * 32 + lane];
        h0.x = fmaf(h0.x, sc.x, sh.x); h0.y = fmaf(h0.y, sc.y, sh.y);
        h0.z = fmaf(h0.z, sc.z, sh.z); h0.w = fmaf(h0.w, sc.w, sh.w);
        if (bnflag) {
            h0.x = fmaxf(h0.x, 0.f); h0.y = fmaxf(h0.y, 0.f);
            h0.z = fmaxf(h0.z, 0.f); h0.w = fmaxf(h0.w, 0.f);
        }
        acc.x += fmaxf(h0.x + e0.x, 0.f);
        acc.y += fmaxf(h0.y + e0.y, 0.f);
        acc.z += fmaxf(h0.z + e0.z, 0.f);
        acc.w += fmaxf(h0.w + e0.w, 0.f);
    }
    float4 hs = h4[(size_t)gw * 32 + lane];
    hs.x = fmaf(hs.x, sc.x, sh.x); hs.y = fmaf(hs.y, sc.y, sh.y);
    hs.z = fmaf(hs.z, sc.z, sh.z); hs.w = fmaf(hs.w, sc.w, sh.w);
    if (bnflag) {
        hs.x = fmaxf(hs.x, 0.f); hs.y = fmaxf(hs.y, 0.f);
        hs.z = fmaxf(hs.z, 0.f); hs.w = fmaxf(hs.w, 0.f);
    }
    acc.x += hs.x; acc.y += hs.y; acc.z += hs.z; acc.w += hs.w;
    ((float4*)outp)[(size_t)gw * 32 + lane] = acc;
}

// ---------------- batchnorm scalars ----------------
__global__ void k_bnzero() {
    int c = threadIdx.x;
    g_bnsum[c] = 0.0;
    g_bnsq[c] = 0.0;
}
__global__ void k_bnfinal(const float* __restrict__ gamma, const float* __restrict__ beta) {
    int c = threadIdx.x;
    double mean = g_bnsum[c] / (double)NN;
    double var = g_bnsq[c] / (double)NN - mean * mean;
    double inv = rsqrt(var + (double)BN_EPS);
    float sc = (float)((double)gamma[c] * inv);
    g_bnscale[c] = sc;
    g_bnshift[c] = (float)((double)beta[c] - mean * (double)sc);
}

// ---------------- pooling (applies final BN+relu on the fly) ----------------
__global__ void k_cnt(const int* __restrict__ batch) {
    int i = blockIdx.x * blockDim.x + threadIdx.x;
    if (i < NN) atomicAdd(&g_cnt[batch[i]], 1);
}
__global__ void __launch_bounds__(128) k_pool(const int* __restrict__ batch) {
    __shared__ int sb[256];
    int c = threadIdx.x;
    int r0 = blockIdx.x * 256;
    for (int i = c; i < 256; i += 128) {
        int r = r0 + i;
        sb[i] = (r < NN) ? batch[r] : -1;
    }
    __syncthreads();
    int rend = min(256, NN - r0);
    if (rend <= 0) return;
    float sc = g_bnscale[c], sh = g_bnshift[c];
    int cur = sb[0];
    float acc = 0.f;
    for (int i = 0; i < rend; i++) {
        int b = sb[i];
        if (b != cur) {
            atomicAdd(&g_pool[cur * HH + c], acc);
            acc = 0.f;
            cur = b;
        }
        acc += fmaxf(fmaf(g_z[(size_t)(r0 + i) * HH + c], sc, sh), 0.f);
    }
    atomicAdd(&g_pool[cur * HH + c], acc);
}

// ---------------- per-graph head ----------------
__global__ void __launch_bounds__(128) k_final(const float* __restrict__ ext,
                                               const float* __restrict__ ew1,
                                               const float* __restrict__ eb1,
                                               const float* __restrict__ ew2,
                                               const float* __restrict__ eb2,
                                               const float* __restrict__ rw1,
                                               const float* __restrict__ rb1,
                                               const float* __restrict__ rw2,
                                               const float* __restrict__ rb2,
                                               float* __restrict__ out) {
    int g = blockIdx.x, c = threadIdx.x;
    __shared__ float shid[HH];
    __shared__ float comb[2 * HH];
    __shared__ float red[HH];
    float xin[EXT_IN];
#pragma unroll
    for (int k = 0; k < EXT_IN; k++) xin[k] = ext[g * EXT_IN + k];
    float hval = eb1[c];
#pragma unroll
    for (int k = 0; k < EXT_IN; k++) hval = fmaf(xin[k], ew1[k * HH + c], hval);
    shid[c] = fmaxf(hval, 0.f);
    __syncthreads();
    float eo = eb2[c];
    for (int k = 0; k < HH; k++) eo = fmaf(shid[k], ew2[k * HH + c], eo);
    float cnt = fmaxf((float)g_cnt[g], 1.f);
    comb[c] = g_pool[g * HH + c] / cnt;
    comb[HH + c] = eo;
    __syncthreads();
    float rh = rb1[c];
    for (int k = 0; k < 2 * HH; k++) rh = fmaf(comb[k], rw1[k * HH + c], rh);
    rh = fmaxf(rh, 0.f);
    red[c] = rh * rw2[c];
    __syncthreads();
    for (int s = 64; s > 0; s >>= 1) {
        if (c < s) red[c] += red[c + s];
        __syncthreads();
    }
    if (c == 0) out[g] = red[0] + rb2[0];
}

// ---------------- host launcher ----------------
extern "C" void kernel_launch(void* const* d_in, const int* in_sizes, int n_in,
                              void* d_out, int out_size) {
    const float* x         = (const float*)d_in[0];
    const float* edge_attr = (const float*)d_in[1];
    const float* externals = (const float*)d_in[2];
    const float* node_w    = (const float*)d_in[3];
    const float* node_b    = (const float*)d_in[4];
    const float* ee_w1     = (const float*)d_in[5];
    const float* ee_b1     = (const float*)d_in[6];
    const float* ee_w2     = (const float*)d_in[7];
    const float* ee_b2     = (const float*)d_in[8];
    const float* conv_w1   = (const float*)d_in[9];
    const float* conv_b1   = (const float*)d_in[10];
    const float* conv_w2   = (const float*)d_in[11];
    const float* conv_b2   = (const float*)d_in[12];
    const float* bn_gamma  = (const float*)d_in[13];
    const float* bn_beta   = (const float*)d_in[14];
    const float* ext_w1    = (const float*)d_in[15];
    const float* ext_b1    = (const float*)d_in[16];
    const float* ext_w2    = (const float*)d_in[17];
    const float* ext_b2    = (const float*)d_in[18];
    const float* reg_w1    = (const float*)d_in[19];
    const float* reg_b1    = (const float*)d_in[20];
    const float* reg_w2    = (const float*)d_in[21];
    const float* reg_b2    = (const float*)d_in[22];
    const int* edge_index  = (const int*)d_in[23];
    const int* batch       = (const int*)d_in[24];
    float* out = (float*)d_out;

    static bool attr_done = false;
    if (!attr_done) {
        cudaFuncSetAttribute(k_edge_tc, cudaFuncAttributeMaxDynamicSharedMemorySize, SMEM_TC);
        cudaFuncSetAttribute(k_conv_tc, cudaFuncAttributeMaxDynamicSharedMemorySize, SMEM_TC);
        attr_done = true;
    }

    float *p_h, *p_z, *p_t;
    cudaGetSymbolAddress((void**)&p_h, g_h);
    cudaGetSymbolAddress((void**)&p_z, g_z);
    cudaGetSymbolAddress((void**)&p_t, g_t);
    __nv_bfloat16* p_wsp;
    cudaGetSymbolAddress((void**)&p_wsp, g_wsp);

    // pre-split weights: m=0: ee_w2; m=1..3: conv_w1[l]; m=4..6: conv_w2[l]
    k_wsplit<<<64, 256>>>(ee_w2, 0);
    for (int l = 0; l < 3; l++) {
        k_wsplit<<<64, 256>>>(conv_w1 + (size_t)l * HH * HH, 1 + l);
        k_wsplit<<<64, 256>>>(conv_w2 + (size_t)l * HH * HH, 4 + l);
    }

    // CSR build (edge_index invariant across layers)
    k_zero<<<(NN + 255) / 256, 256>>>();
    k_degree<<<(EE + 255) / 256, 256>>>(edge_index + EE);
    k_scan<<<1, 1024>>>();
    k_fillcsr<<<(EE + 255) / 256, 256>>>(edge_index);

    // encoders
    k_node_enc<<<(NN + 63) / 64, 128>>>(x, node_w, node_b);
    k_edge_tc<<<EE / 128, 256, SMEM_TC>>>(edge_attr, ee_w1, ee_b1, p_wsp, ee_b2);

    // 3x (aggregate [+prev BN fused] -> fused conv MLP [+BN stats] -> BN scalars)
    for (int l = 0; l < 3; l++) {
        k_bnzero<<<1, 128>>>();
        k_aggregate<<<(NN * 32 + 255) / 256, 256>>>(l == 0 ? p_h : p_z, p_t, l > 0 ? 1 : 0);
        k_conv_tc<<<(NN + 127) / 128, 256, SMEM_TC>>>(
            p_t,
            p_wsp + (size_t)(1 + l) * 2 * HH * HH,
            p_wsp + (size_t)(4 + l) * 2 * HH * HH,
            conv_b1 + (size_t)l * HH, conv_b2 + (size_t)l * HH, p_z, NN);
        k_bnfinal<<<1, 128>>>(bn_gamma + (size_t)l * HH, bn_beta + (size_t)l * HH);
    }

    // pooling (applies layer-2 BN+relu) + head
    k_cnt<<<(NN + 255) / 256, 256>>>(batch);
    k_pool<<<(NN + 255) / 256, 128>>>(batch);
    k_final<<<GG, 128>>>(externals, ext_w1, ext_b1, ext_w2, ext_b2,
                         reg_w1, reg_b1, reg_w2, reg_b2, out);
}

// round 7
// speedup vs baseline: 1.4503x; 1.1795x over previous
#include <cuda_runtime.h>
#include <cuda_bf16.h>
#include <cuda_fp16.h>
#include <cstdint>

#define NN 50000
#define EE 640000
#define GG 256
#define HH 128
#define NODE_IN 32
#define EDGE_IN 16
#define EXT_IN 8
#define BN_EPS 1e-5f
#define SA 136            // padded fp16 row stride (elements): 272B rows, conflict-free
#define SMEM_BIG 77824

// ---------------- device scratch (static; no allocations) ----------------
__device__ __align__(16) float  g_h[(size_t)NN * HH];
__device__ __align__(16) __half g_e[(size_t)EE * HH];   // CSR-ordered edge features (fp16)
__device__ __align__(16) float  g_ea[(size_t)EE * EDGE_IN]; // CSR-ordered edge attrs
__device__ __align__(16) float  g_z[(size_t)NN * HH];
__device__ __align__(16) float  g_t[(size_t)NN * HH];
__device__ __align__(16) float  g_pool[GG * HH];
__device__ int    g_cnt[GG];
__device__ int    g_rowptr[NN + 1];
__device__ int    g_fill[NN];
__device__ int    g_src[EE];    // src node per CSR slot
__device__ double g_bnsum[HH];
__device__ double g_bnsq[HH];
__device__ __align__(16) float g_bnscale[HH];
__device__ __align__(16) float g_bnshift[HH];
// fp16 weights, transposed to [n][k]: m=0 ee_w2, 1..3 conv_w1, 4..6 conv_w2
__device__ __align__(16) __half g_wh[7 * HH * HH];

// ---------------- mma.sync fp16 ----------------
__device__ __forceinline__ void mma_fp16(float c[4], unsigned a0, unsigned a1,
                                         unsigned a2, unsigned a3,
                                         unsigned b0, unsigned b1) {
    asm("mma.sync.aligned.m16n8k16.row.col.f32.f16.f16.f32 "
        "{%0,%1,%2,%3}, {%4,%5,%6,%7}, {%8,%9}, {%0,%1,%2,%3};"
        : "+f"(c[0]), "+f"(c[1]), "+f"(c[2]), "+f"(c[3])
        : "r"(a0), "r"(a1), "r"(a2), "r"(a3), "r"(b0), "r"(b1));
}

// C[16x128] per warp = A(16x128 fp16 smem) @ W(128x128 fp16 smem, [n][k])
__device__ __forceinline__ void gemm_fp16(const __half* A, const __half* W,
                                          float c[16][4], int rb, int lane) {
    int g = lane >> 2, t2 = (lane & 3) * 2;
    const __half* ar0 = A + (rb + g) * SA + t2;
    const __half* ar1 = A + (rb + g + 8) * SA + t2;
    for (int ks = 0; ks < 8; ks++) {
        int k0 = ks * 16;
        unsigned a0 = *(const unsigned*)(ar0 + k0);
        unsigned a1 = *(const unsigned*)(ar1 + k0);
        unsigned a2 = *(const unsigned*)(ar0 + k0 + 8);
        unsigned a3 = *(const unsigned*)(ar1 + k0 + 8);
#pragma unroll
        for (int nb = 0; nb < 16; nb++) {
            const __half* w = W + (nb * 8 + g) * SA + k0 + t2;
            unsigned b0 = *(const unsigned*)(w);
            unsigned b1 = *(const unsigned*)(w + 8);
            mma_fp16(c[nb], a0, a1, a2, a3, b0, b1);
        }
    }
}

// copy one 128x128 fp16 matrix ([n][k] contiguous) into padded (SA) smem
__device__ __forceinline__ void copy_w(const __half* __restrict__ src,
                                       __half* dst, int tid) {
    const uint4* s4 = (const uint4*)src;
    for (int i = tid; i < 2048; i += 256) {
        int n = i >> 4, ch = i & 15;
        *(uint4*)((char*)dst + n * 272 + ch * 16) = s4[i];
    }
}

// ---------------- weight prep (fp32 [k][n] -> fp16 [n][k]) ----------------
__global__ void k_wprep(const float* __restrict__ w, int m) {
    int idx = blockIdx.x * 256 + threadIdx.x;
    if (idx >= HH * HH) return;
    int k = idx >> 7, n = idx & 127;
    g_wh[(size_t)m * HH * HH + n * HH + k] = __float2half(w[k * HH + n]);
}

// ---------------- edge encoder: g_e[slot] = relu(g_ea@W1+b1)@W2+b2 (fp16 out) ----------------
__global__ void __launch_bounds__(256) k_edge_tc(const float* __restrict__ w1,
                                                 const float* __restrict__ b1,
                                                 const __half* __restrict__ w2h,
                                                 const float* __restrict__ b2) {
    extern __shared__ char smem[];
    float* Ea = (float*)smem;                       // 128*16 f32 = 8KB
    __half* Ah = (__half*)(smem + 8192);            // 128*SA fp16
    __half* Wh = Ah + 128 * SA;
    int tid = threadIdx.x, lane = tid & 31, wid = tid >> 5;
    int e0 = blockIdx.x * 128;

    const float4* ea4 = (const float4*)g_ea;
    float4* Ea4 = (float4*)Ea;
#pragma unroll
    for (int i = 0; i < 2; i++) Ea4[tid + 256 * i] = ea4[(size_t)e0 * 4 + tid + 256 * i];
    copy_w(w2h, Wh, tid);
    __syncthreads();

    // phase 1: hidden = relu(ea@W1+b1) -> fp16
    {
        int col = tid & 127, rh = tid >> 7;
        float w1r[16];
#pragma unroll
        for (int k = 0; k < 16; k++) w1r[k] = w1[k * HH + col];
        float bb = b1[col];
        for (int r = rh * 64; r < rh * 64 + 64; r++) {
            const float4* er = (const float4*)(Ea + r * EDGE_IN);
            float4 x0 = er[0], x1 = er[1], x2 = er[2], x3 = er[3];
            float s = bb;
            s = fmaf(x0.x, w1r[0], s);  s = fmaf(x0.y, w1r[1], s);
            s = fmaf(x0.z, w1r[2], s);  s = fmaf(x0.w, w1r[3], s);
            s = fmaf(x1.x, w1r[4], s);  s = fmaf(x1.y, w1r[5], s);
            s = fmaf(x1.z, w1r[6], s);  s = fmaf(x1.w, w1r[7], s);
            s = fmaf(x2.x, w1r[8], s);  s = fmaf(x2.y, w1r[9], s);
            s = fmaf(x2.z, w1r[10], s); s = fmaf(x2.w, w1r[11], s);
            s = fmaf(x3.x, w1r[12], s); s = fmaf(x3.y, w1r[13], s);
            s = fmaf(x3.z, w1r[14], s); s = fmaf(x3.w, w1r[15], s);
            Ah[r * SA + col] = __float2half(fmaxf(s, 0.f));
        }
    }
    __syncthreads();

    float c[16][4];
#pragma unroll
    for (int i = 0; i < 16; i++)
#pragma unroll
        for (int j = 0; j < 4; j++) c[i][j] = 0.f;
    gemm_fp16(Ah, Wh, c, wid * 16, lane);

    // stage result (with bias) back into Ah as fp16, own rows only
    int g = lane >> 2, t2 = (lane & 3) * 2;
    int rb = wid * 16;
#pragma unroll
    for (int nb = 0; nb < 16; nb++) {
        int col = nb * 8 + t2;
        float2 bb = *(const float2*)(b2 + col);
        *(__half2*)(Ah + (rb + g) * SA + col)     = __floats2half2_rn(c[nb][0] + bb.x, c[nb][1] + bb.y);
        *(__half2*)(Ah + (rb + g + 8) * SA + col) = __floats2half2_rn(c[nb][2] + bb.x, c[nb][3] + bb.y);
    }
    __syncthreads();

    // coalesced copy-out: 128 rows x 256B
    uint4* dst = (uint4*)(g_e + (size_t)e0 * HH);
    for (int i = tid; i < 2048; i += 256) {
        int r = i >> 4, ch = i & 15;
        dst[i] = *(const uint4*)((const char*)Ah + r * 272 + ch * 16);
    }
}

// -------- fused conv MLP: z = (relu(A@W1+b1))@W2+b2, + BN partial stats --------
__global__ void __launch_bounds__(256) k_conv_tc(const float* __restrict__ A,
                                                 const __half* __restrict__ w1h,
                                                 const __half* __restrict__ w2h,
                                                 const float* __restrict__ b1,
                                                 const float* __restrict__ b2,
                                                 float* __restrict__ Cc, int M) {
    extern __shared__ char smem[];
    __half* Ah = (__half*)smem;
    __half* Wh = Ah + 128 * SA;
    float* redS = (float*)(smem + 2 * 128 * SA * 2);   // [8][128]
    float* redQ = redS + 8 * 128;                      // [8][128]
    int tid = threadIdx.x, lane = tid & 31, wid = tid >> 5;
    int rowBase = blockIdx.x * 128;

    const float4* A4 = (const float4*)A;
    for (int idx = tid; idx < 128 * 32; idx += 256) {
        int r = idx >> 5, q = idx & 31;
        int gr = rowBase + r;
        float4 v = make_float4(0.f, 0.f, 0.f, 0.f);
        if (gr < M) v = A4[(size_t)gr * 32 + q];
        *(__half2*)(Ah + r * SA + q * 4)     = __floats2half2_rn(v.x, v.y);
        *(__half2*)(Ah + r * SA + q * 4 + 2) = __floats2half2_rn(v.z, v.w);
    }
    copy_w(w1h, Wh, tid);
    __syncthreads();

    float c[16][4];
#pragma unroll
    for (int i = 0; i < 16; i++)
#pragma unroll
        for (int j = 0; j < 4; j++) c[i][j] = 0.f;
    gemm_fp16(Ah, Wh, c, wid * 16, lane);

    int g = lane >> 2, t2 = (lane & 3) * 2;
    int rb = wid * 16;
    // hidden = relu(c+b1) -> own rows of Ah
#pragma unroll
    for (int nb = 0; nb < 16; nb++) {
        int col = nb * 8 + t2;
        float2 bb = *(const float2*)(b1 + col);
        *(__half2*)(Ah + (rb + g) * SA + col) =
            __floats2half2_rn(fmaxf(c[nb][0] + bb.x, 0.f), fmaxf(c[nb][1] + bb.y, 0.f));
        *(__half2*)(Ah + (rb + g + 8) * SA + col) =
            __floats2half2_rn(fmaxf(c[nb][2] + bb.x, 0.f), fmaxf(c[nb][3] + bb.y, 0.f));
    }
    __syncthreads();
    copy_w(w2h, Wh, tid);
    __syncthreads();

#pragma unroll
    for (int i = 0; i < 16; i++)
#pragma unroll
        for (int j = 0; j < 4; j++) c[i][j] = 0.f;
    gemm_fp16(Ah, Wh, c, rb, lane);

    // epilogue: z -> global + BN column partial sums
    int r0g = rowBase + rb + g, r1g = r0g + 8;
    bool v0 = r0g < M, v1 = r1g < M;
#pragma unroll
    for (int nb = 0; nb < 16; nb++) {
        int col = nb * 8 + t2;
        float2 bb = *(const float2*)(b2 + col);
        float z00 = c[nb][0] + bb.x, z01 = c[nb][1] + bb.y;
        float z10 = c[nb][2] + bb.x, z11 = c[nb][3] + bb.y;
        if (v0) *(float2*)(Cc + (size_t)r0g * HH + col) = make_float2(z00, z01);
        if (v1) *(float2*)(Cc + (size_t)r1g * HH + col) = make_float2(z10, z11);
        float s0 = (v0 ? z00 : 0.f) + (v1 ? z10 : 0.f);
        float s1 = (v0 ? z01 : 0.f) + (v1 ? z11 : 0.f);
        float q0 = (v0 ? z00 * z00 : 0.f) + (v1 ? z10 * z10 : 0.f);
        float q1 = (v0 ? z01 * z01 : 0.f) + (v1 ? z11 * z11 : 0.f);
#pragma unroll
        for (int m = 4; m <= 16; m <<= 1) {
            s0 += __shfl_xor_sync(0xffffffffu, s0, m);
            s1 += __shfl_xor_sync(0xffffffffu, s1, m);
            q0 += __shfl_xor_sync(0xffffffffu, q0, m);
            q1 += __shfl_xor_sync(0xffffffffu, q1, m);
        }
        if (lane < 4) {
            redS[wid * 128 + col] = s0;
            redS[wid * 128 + col + 1] = s1;
            redQ[wid * 128 + col] = q0;
            redQ[wid * 128 + col + 1] = q1;
        }
    }
    __syncthreads();
    if (tid < 128) {
        float s = 0.f;
#pragma unroll
        for (int w = 0; w < 8; w++) s += redS[w * 128 + tid];
        atomicAdd(&g_bnsum[tid], (double)s);
    } else {
        int col = tid - 128;
        float s = 0.f;
#pragma unroll
        for (int w = 0; w < 8; w++) s += redQ[w * 128 + col];
        atomicAdd(&g_bnsq[col], (double)s);
    }
}

// ---------------- node encoder: g_h = x @ node_w + node_b ----------------
__global__ void __launch_bounds__(128) k_node_enc(const float* __restrict__ x,
                                                  const float* __restrict__ w,
                                                  const float* __restrict__ b) {
    __shared__ float Xs[64 * NODE_IN];
    __shared__ float Wn[NODE_IN * HH];
    int tid = threadIdx.x;
    int rowBase = blockIdx.x * 64;
    const float4* W4 = (const float4*)w;
    float4* Wn4 = (float4*)Wn;
#pragma unroll
    for (int i = 0; i < 8; i++) Wn4[tid + 128 * i] = W4[tid + 128 * i];
    const float4* X4 = (const float4*)x;
    float4* Xs4 = (float4*)Xs;
#pragma unroll
    for (int i = 0; i < 4; i++) {
        int idx = tid + 128 * i;
        int r = idx >> 3;
        int gr = rowBase + r;
        float4 v = make_float4(0.f, 0.f, 0.f, 0.f);
        if (gr < NN) v = X4[(size_t)gr * 8 + (idx & 7)];
        Xs4[idx] = v;
    }
    __syncthreads();
    float wr[32];
#pragma unroll
    for (int k = 0; k < 32; k++) wr[k] = Wn[k * HH + tid];
    float bv = b[tid];
    for (int r = 0; r < 64; r++) {
        int gr = rowBase + r;
        if (gr >= NN) break;
        const float4* xr = (const float4*)(Xs + r * NODE_IN);
        float s = bv;
#pragma unroll
        for (int q = 0; q < 8; q++) {
            float4 xv = xr[q];
            s = fmaf(xv.x, wr[4 * q + 0], s);
            s = fmaf(xv.y, wr[4 * q + 1], s);
            s = fmaf(xv.z, wr[4 * q + 2], s);
            s = fmaf(xv.w, wr[4 * q + 3], s);
        }
        g_h[(size_t)gr * HH + tid] = s;
    }
}

// ---------------- CSR build ----------------
__global__ void k_zero() {
    int i = blockIdx.x * blockDim.x + threadIdx.x;
    if (i < NN) g_fill[i] = 0;
    if (i < GG * HH) g_pool[i] = 0.f;
    if (i < GG) g_cnt[i] = 0;
}
__global__ void k_degree(const int* __restrict__ dst) {
    int i = blockIdx.x * blockDim.x + threadIdx.x;
    if (i < EE) atomicAdd(&g_fill[dst[i]], 1);
}
__global__ void k_scan() {
    __shared__ int sdata[1024];
    __shared__ int carry;
    int tid = threadIdx.x;
    if (tid == 0) carry = 0;
    __syncthreads();
    for (int base = 0; base < NN; base += 1024) {
        int v = (base + tid < NN) ? g_fill[base + tid] : 0;
        sdata[tid] = v;
        __syncthreads();
        for (int off = 1; off < 1024; off <<= 1) {
            int t = (tid >= off) ? sdata[tid - off] : 0;
            __syncthreads();
            sdata[tid] += t;
            __syncthreads();
        }
        int cb = carry;
        if (base + tid < NN) {
            g_rowptr[base + tid] = cb + sdata[tid] - v;
            g_fill[base + tid] = 0;
        }
        __syncthreads();
        if (tid == 0) carry = cb + sdata[1023];
        __syncthreads();
    }
    if (tid == 0) g_rowptr[NN] = carry;
}
// fill CSR and permute edge_attr into slot order
__global__ void k_fillcsr(const int* __restrict__ ei, const float* __restrict__ ea) {
    int i = blockIdx.x * blockDim.x + threadIdx.x;
    if (i < EE) {
        int s = ei[i];
        int d = ei[EE + i];
        int p = atomicAdd(&g_fill[d], 1);
        int slot = g_rowptr[d] + p;
        g_src[slot] = s;
        const float4* src4 = (const float4*)(ea + (size_t)i * EDGE_IN);
        float4* dst4 = (float4*)(g_ea + (size_t)slot * EDGE_IN);
        dst4[0] = src4[0];
        dst4[1] = src4[1];
        dst4[2] = src4[2];
        dst4[3] = src4[3];
    }
}

// ---- aggregation: out = h_self + sum relu(h[src]+e), h = bn? relu(z*sc+sh) : z ----
__global__ void __launch_bounds__(256) k_aggregate(const float* __restrict__ in,
                                                   float* __restrict__ outp, int bnflag) {
    int gw = (blockIdx.x * 256 + threadIdx.x) >> 5;
    int lane = threadIdx.x & 31;
    if (gw >= NN) return;
    float4 sc = make_float4(1.f, 1.f, 1.f, 1.f);
    float4 sh = make_float4(0.f, 0.f, 0.f, 0.f);
    if (bnflag) {
        sc = ((const float4*)g_bnscale)[lane];
        sh = ((const float4*)g_bnshift)[lane];
    }
    int beg = g_rowptr[gw], end = g_rowptr[gw + 1];
    const float4* h4 = (const float4*)in;
    const uint2* e2 = (const uint2*)g_e;
    float4 acc = make_float4(0.f, 0.f, 0.f, 0.f);
    for (int j = beg; j < end; j++) {
        int s0 = g_src[j];
        uint2 ew = e2[(size_t)j * 32 + lane];
        float2 ea = __half22float2(*(__half2*)&ew.x);
        float2 eb = __half22float2(*(__half2*)&ew.y);
        float4 h0 = h4[(size_t)s0 * 32 + lane];
        h0.x = fmaf(h0.x, sc.x, sh.x); h0.y = fmaf(h0.y, sc.y, sh.y);
        h0.z = fmaf(h0.z, sc.z, sh.z); h0.w = fmaf(h0.w, sc.w, sh.w);
        if (bnflag) {
            h0.x = fmaxf(h0.x, 0.f); h0.y = fmaxf(h0.y, 0.f);
            h0.z = fmaxf(h0.z, 0.f); h0.w = fmaxf(h0.w, 0.f);
        }
        acc.x += fmaxf(h0.x + ea.x, 0.f);
        acc.y += fmaxf(h0.y + ea.y, 0.f);
        acc.z += fmaxf(h0.z + eb.x, 0.f);
        acc.w += fmaxf(h0.w + eb.y, 0.f);
    }
    float4 hs = h4[(size_t)gw * 32 + lane];
    hs.x = fmaf(hs.x, sc.x, sh.x); hs.y = fmaf(hs.y, sc.y, sh.y);
    hs.z = fmaf(hs.z, sc.z, sh.z); hs.w = fmaf(hs.w, sc.w, sh.w);
    if (bnflag) {
        hs.x = fmaxf(hs.x, 0.f); hs.y = fmaxf(hs.y, 0.f);
        hs.z = fmaxf(hs.z, 0.f); hs.w = fmaxf(hs.w, 0.f);
    }
    acc.x += hs.x; acc.y += hs.y; acc.z += hs.z; acc.w += hs.w;
    ((float4*)outp)[(size_t)gw * 32 + lane] = acc;
}

// ---------------- batchnorm scalars ----------------
__global__ void k_bnzero() {
    int c = threadIdx.x;
    g_bnsum[c] = 0.0;
    g_bnsq[c] = 0.0;
}
__global__ void k_bnfinal(const float* __restrict__ gamma, const float* __restrict__ beta) {
    int c = threadIdx.x;
    double mean = g_bnsum[c] / (double)NN;
    double var = g_bnsq[c] / (double)NN - mean * mean;
    double inv = rsqrt(var + (double)BN_EPS);
    float sc = (float)((double)gamma[c] * inv);
    g_bnscale[c] = sc;
    g_bnshift[c] = (float)((double)beta[c] - mean * (double)sc);
}

// ---------------- pooling (applies final BN+relu on the fly) ----------------
__global__ void k_cnt(const int* __restrict__ batch) {
    int i = blockIdx.x * blockDim.x + threadIdx.x;
    if (i < NN) atomicAdd(&g_cnt[batch[i]], 1);
}
__global__ void __launch_bounds__(128) k_pool(const int* __restrict__ batch) {
    __shared__ int sb[256];
    int c = threadIdx.x;
    int r0 = blockIdx.x * 256;
    for (int i = c; i < 256; i += 128) {
        int r = r0 + i;
        sb[i] = (r < NN) ? batch[r] : -1;
    }
    __syncthreads();
    int rend = min(256, NN - r0);
    if (rend <= 0) return;
    float sc = g_bnscale[c], sh = g_bnshift[c];
    int cur = sb[0];
    float acc = 0.f;
    for (int i = 0; i < rend; i++) {
        int b = sb[i];
        if (b != cur) {
            atomicAdd(&g_pool[cur * HH + c], acc);
            acc = 0.f;
            cur = b;
        }
        acc += fmaxf(fmaf(g_z[(size_t)(r0 + i) * HH + c], sc, sh), 0.f);
    }
    atomicAdd(&g_pool[cur * HH + c], acc);
}

// ---------------- per-graph head ----------------
__global__ void __launch_bounds__(128) k_final(const float* __restrict__ ext,
                                               const float* __restrict__ ew1,
                                               const float* __restrict__ eb1,
                                               const float* __restrict__ ew2,
                                               const float* __restrict__ eb2,
                                               const float* __restrict__ rw1,
                                               const float* __restrict__ rb1,
                                               const float* __restrict__ rw2,
                                               const float* __restrict__ rb2,
                                               float* __restrict__ out) {
    int g = blockIdx.x, c = threadIdx.x;
    __shared__ float shid[HH];
    __shared__ float comb[2 * HH];
    __shared__ float red[HH];
    float xin[EXT_IN];
#pragma unroll
    for (int k = 0; k < EXT_IN; k++) xin[k] = ext[g * EXT_IN + k];
    float hval = eb1[c];
#pragma unroll
    for (int k = 0; k < EXT_IN; k++) hval = fmaf(xin[k], ew1[k * HH + c], hval);
    shid[c] = fmaxf(hval, 0.f);
    __syncthreads();
    float eo = eb2[c];
    for (int k = 0; k < HH; k++) eo = fmaf(shid[k], ew2[k * HH + c], eo);
    float cnt = fmaxf((float)g_cnt[g], 1.f);
    comb[c] = g_pool[g * HH + c] / cnt;
    comb[HH + c] = eo;
    __syncthreads();
    float rh = rb1[c];
    for (int k = 0; k < 2 * HH; k++) rh = fmaf(comb[k], rw1[k * HH + c], rh);
    rh = fmaxf(rh, 0.f);
    red[c] = rh * rw2[c];
    __syncthreads();
    for (int s = 64; s > 0; s >>= 1) {
        if (c < s) red[c] += red[c + s];
        __syncthreads();
    }
    if (c == 0) out[g] = red[0] + rb2[0];
}

// ---------------- host launcher ----------------
extern "C" void kernel_launch(void* const* d_in, const int* in_sizes, int n_in,
                              void* d_out, int out_size) {
    const float* x         = (const float*)d_in[0];
    const float* edge_attr = (const float*)d_in[1];
    const float* externals = (const float*)d_in[2];
    const float* node_w    = (const float*)d_in[3];
    const float* node_b    = (const float*)d_in[4];
    const float* ee_w1     = (const float*)d_in[5];
    const float* ee_b1     = (const float*)d_in[6];
    const float* ee_w2     = (const float*)d_in[7];
    const float* ee_b2     = (const float*)d_in[8];
    const float* conv_w1   = (const float*)d_in[9];
    const float* conv_b1   = (const float*)d_in[10];
    const float* conv_w2   = (const float*)d_in[11];
    const float* conv_b2   = (const float*)d_in[12];
    const float* bn_gamma  = (const float*)d_in[13];
    const float* bn_beta   = (const float*)d_in[14];
    const float* ext_w1    = (const float*)d_in[15];
    const float* ext_b1    = (const float*)d_in[16];
    const float* ext_w2    = (const float*)d_in[17];
    const float* ext_b2    = (const float*)d_in[18];
    const float* reg_w1    = (const float*)d_in[19];
    const float* reg_b1    = (const float*)d_in[20];
    const float* reg_w2    = (const float*)d_in[21];
    const float* reg_b2    = (const float*)d_in[22];
    const int* edge_index  = (const int*)d_in[23];
    const int* batch       = (const int*)d_in[24];
    float* out = (float*)d_out;

    static bool attr_done = false;
    if (!attr_done) {
        cudaFuncSetAttribute(k_edge_tc, cudaFuncAttributeMaxDynamicSharedMemorySize, SMEM_BIG);
        cudaFuncSetAttribute(k_conv_tc, cudaFuncAttributeMaxDynamicSharedMemorySize, SMEM_BIG);
        attr_done = true;
    }

    float *p_h, *p_z, *p_t;
    cudaGetSymbolAddress((void**)&p_h, g_h);
    cudaGetSymbolAddress((void**)&p_z, g_z);
    cudaGetSymbolAddress((void**)&p_t, g_t);
    __half* p_wh;
    cudaGetSymbolAddress((void**)&p_wh, g_wh);

    // weight prep: m=0 ee_w2; 1..3 conv_w1; 4..6 conv_w2
    k_wprep<<<64, 256>>>(ee_w2, 0);
    for (int l = 0; l < 3; l++) {
        k_wprep<<<64, 256>>>(conv_w1 + (size_t)l * HH * HH, 1 + l);
        k_wprep<<<64, 256>>>(conv_w2 + (size_t)l * HH * HH, 4 + l);
    }

    // CSR build + edge_attr permute (edge_index invariant across layers)
    k_zero<<<(NN + 255) / 256, 256>>>();
    k_degree<<<(EE + 255) / 256, 256>>>(edge_index + EE);
    k_scan<<<1, 1024>>>();
    k_fillcsr<<<(EE + 255) / 256, 256>>>(edge_index, edge_attr);

    // encoders
    k_node_enc<<<(NN + 63) / 64, 128>>>(x, node_w, node_b);
    k_edge_tc<<<EE / 128, 256, SMEM_BIG>>>(ee_w1, ee_b1, p_wh, ee_b2);

    // 3x (aggregate [+prev BN fused] -> fused conv MLP [+BN stats] -> BN scalars)
    for (int l = 0; l < 3; l++) {
        k_bnzero<<<1, 128>>>();
        k_aggregate<<<(NN * 32 + 255) / 256, 256>>>(l == 0 ? p_h : p_z, p_t, l > 0 ? 1 : 0);
        k_conv_tc<<<(NN + 127) / 128, 256, SMEM_BIG>>>(
            p_t,
            p_wh + (size_t)(1 + l) * HH * HH,
            p_wh + (size_t)(4 + l) * HH * HH,
            conv_b1 + (size_t)l * HH, conv_b2 + (size_t)l * HH, p_z, NN);
        k_bnfinal<<<1, 128>>>(bn_gamma + (size_t)l * HH, bn_beta + (size_t)l * HH);
    }

    // pooling (applies layer-3 BN+relu) + head
    k_cnt<<<(NN + 255) / 256, 256>>>(batch);
    k_pool<<<(NN + 255) / 256, 128>>>(batch);
    k_final<<<GG, 128>>>(externals, ext_w1, ext_b1, ext_w2, ext_b2,
                         reg_w1, reg_b1, reg_w2, reg_b2, out);
}

// round 10
// speedup vs baseline: 2.1817x; 1.5043x over previous
#include <cuda_runtime.h>
#include <cuda_bf16.h>
#include <cuda_fp16.h>
#include <cstdint>

#define NN 50000
#define EE 640000
#define GG 256
#define HH 128
#define NODE_IN 32
#define EDGE_IN 16
#define EXT_IN 8
#define BN_EPS 1e-5f
#define SA 136            // padded fp16 row stride (elements): 272B rows, conflict-free
#define SMEM_BIG 77824

// ---------------- device scratch (static; no allocations) ----------------
__device__ __align__(16) __half g_hf[(size_t)NN * HH];      // fp16 node state (pre-BN z or h0)
__device__ __align__(16) __half g_e[(size_t)EE * HH];       // CSR-ordered edge features (fp16)
__device__ __align__(16) float  g_ea[(size_t)EE * EDGE_IN]; // CSR-ordered edge attrs
__device__ __align__(16) float  g_z[(size_t)NN * HH];       // fp32 z (for BN'd pool at end)
__device__ __align__(16) __half g_t[(size_t)NN * HH];       // aggregate output (conv input)
__device__ __align__(16) float  g_pool[GG * HH];
__device__ int    g_cnt[GG];
__device__ int    g_rowptr[NN + 1];
__device__ int    g_fill[NN];
__device__ int    g_src[EE];    // src node per CSR slot
__device__ double g_bnsum[HH];
__device__ double g_bnsq[HH];
__device__ __align__(16) float g_bnscale[HH];
__device__ __align__(16) float g_bnshift[HH];
// fp16 weights, transposed to [n][k]: m=0 ee_w2, 1..3 conv_w1, 4..6 conv_w2
__device__ __align__(16) __half g_wh[7 * HH * HH];

// ---------------- helpers ----------------
__device__ __forceinline__ float4 h4f(uint2 w) {
    float2 a = __half22float2(*(__half2*)&w.x);
    float2 b = __half22float2(*(__half2*)&w.y);
    return make_float4(a.x, a.y, b.x, b.y);
}
__device__ __forceinline__ uint2 f4h(float4 v) {
    uint2 r;
    *(__half2*)&r.x = __floats2half2_rn(v.x, v.y);
    *(__half2*)&r.y = __floats2half2_rn(v.z, v.w);
    return r;
}

// ---------------- mma.sync fp16 ----------------
__device__ __forceinline__ void mma_fp16(float c[4], unsigned a0, unsigned a1,
                                         unsigned a2, unsigned a3,
                                         unsigned b0, unsigned b1) {
    asm("mma.sync.aligned.m16n8k16.row.col.f32.f16.f16.f32 "
        "{%0,%1,%2,%3}, {%4,%5,%6,%7}, {%8,%9}, {%0,%1,%2,%3};"
        : "+f"(c[0]), "+f"(c[1]), "+f"(c[2]), "+f"(c[3])
        : "r"(a0), "r"(a1), "r"(a2), "r"(a3), "r"(b0), "r"(b1));
}

// C[16x128] per warp = A(16x128 fp16 smem) @ W(128x128 fp16 smem, [n][k])
__device__ __forceinline__ void gemm_fp16(const __half* A, const __half* W,
                                          float c[16][4], int rb, int lane) {
    int g = lane >> 2, t2 = (lane & 3) * 2;
    const __half* ar0 = A + (rb + g) * SA + t2;
    const __half* ar1 = A + (rb + g + 8) * SA + t2;
    for (int ks = 0; ks < 8; ks++) {
        int k0 = ks * 16;
        unsigned a0 = *(const unsigned*)(ar0 + k0);
        unsigned a1 = *(const unsigned*)(ar1 + k0);
        unsigned a2 = *(const unsigned*)(ar0 + k0 + 8);
        unsigned a3 = *(const unsigned*)(ar1 + k0 + 8);
#pragma unroll
        for (int nb = 0; nb < 16; nb++) {
            const __half* w = W + (nb * 8 + g) * SA + k0 + t2;
            unsigned b0 = *(const unsigned*)(w);
            unsigned b1 = *(const unsigned*)(w + 8);
            mma_fp16(c[nb], a0, a1, a2, a3, b0, b1);
        }
    }
}

// copy one 128x128 fp16 matrix ([n][k] contiguous) into padded (SA) smem
__device__ __forceinline__ void copy_w(const __half* __restrict__ src,
                                       __half* dst, int tid) {
    const uint4* s4 = (const uint4*)src;
    for (int i = tid; i < 2048; i += 256) {
        int n = i >> 4, ch = i & 15;
        *(uint4*)((char*)dst + n * 272 + ch * 16) = s4[i];
    }
}

// ---------------- weight prep (fp32 [k][n] -> fp16 [n][k]), all 7 mats ----------------
__global__ void k_wprep(const float* __restrict__ ee_w2,
                        const float* __restrict__ conv_w1,
                        const float* __restrict__ conv_w2) {
    int m = blockIdx.y;
    const float* w = (m == 0) ? ee_w2
                   : (m <= 3) ? conv_w1 + (size_t)(m - 1) * HH * HH
                              : conv_w2 + (size_t)(m - 4) * HH * HH;
    int idx = blockIdx.x * 256 + threadIdx.x;
    if (idx >= HH * HH) return;
    int k = idx >> 7, n = idx & 127;
    g_wh[(size_t)m * HH * HH + n * HH + k] = __float2half(w[k * HH + n]);
}

// ---------------- edge encoder: g_e[slot] = relu(g_ea@W1+b1)@W2+b2 (fp16 out) ----------------
__global__ void __launch_bounds__(256) k_edge_tc(const float* __restrict__ w1,
                                                 const float* __restrict__ b1,
                                                 const __half* __restrict__ w2h,
                                                 const float* __restrict__ b2) {
    extern __shared__ char smem[];
    float* Ea = (float*)smem;                       // 128*16 f32 = 8KB
    __half* Ah = (__half*)(smem + 8192);            // 128*SA fp16
    __half* Wh = Ah + 128 * SA;
    int tid = threadIdx.x, lane = tid & 31, wid = tid >> 5;
    int e0 = blockIdx.x * 128;

    const float4* ea4 = (const float4*)g_ea;
    float4* Ea4 = (float4*)Ea;
#pragma unroll
    for (int i = 0; i < 2; i++) Ea4[tid + 256 * i] = ea4[(size_t)e0 * 4 + tid + 256 * i];
    copy_w(w2h, Wh, tid);
    __syncthreads();

    // phase 1: hidden = relu(ea@W1+b1) -> fp16
    {
        int col = tid & 127, rh = tid >> 7;
        float w1r[16];
#pragma unroll
        for (int k = 0; k < 16; k++) w1r[k] = w1[k * HH + col];
        float bb = b1[col];
        for (int r = rh * 64; r < rh * 64 + 64; r++) {
            const float4* er = (const float4*)(Ea + r * EDGE_IN);
            float4 x0 = er[0], x1 = er[1], x2 = er[2], x3 = er[3];
            float s = bb;
            s = fmaf(x0.x, w1r[0], s);  s = fmaf(x0.y, w1r[1], s);
            s = fmaf(x0.z, w1r[2], s);  s = fmaf(x0.w, w1r[3], s);
            s = fmaf(x1.x, w1r[4], s);  s = fmaf(x1.y, w1r[5], s);
            s = fmaf(x1.z, w1r[6], s);  s = fmaf(x1.w, w1r[7], s);
            s = fmaf(x2.x, w1r[8], s);  s = fmaf(x2.y, w1r[9], s);
            s = fmaf(x2.z, w1r[10], s); s = fmaf(x2.w, w1r[11], s);
            s = fmaf(x3.x, w1r[12], s); s = fmaf(x3.y, w1r[13], s);
            s = fmaf(x3.z, w1r[14], s); s = fmaf(x3.w, w1r[15], s);
            Ah[r * SA + col] = __float2half(fmaxf(s, 0.f));
        }
    }
    __syncthreads();

    float c[16][4];
#pragma unroll
    for (int i = 0; i < 16; i++)
#pragma unroll
        for (int j = 0; j < 4; j++) c[i][j] = 0.f;
    gemm_fp16(Ah, Wh, c, wid * 16, lane);

    // stage result (with bias) back into Ah as fp16, own rows only
    int g = lane >> 2, t2 = (lane & 3) * 2;
    int rb = wid * 16;
#pragma unroll
    for (int nb = 0; nb < 16; nb++) {
        int col = nb * 8 + t2;
        float2 bb = *(const float2*)(b2 + col);
        *(__half2*)(Ah + (rb + g) * SA + col)     = __floats2half2_rn(c[nb][0] + bb.x, c[nb][1] + bb.y);
        *(__half2*)(Ah + (rb + g + 8) * SA + col) = __floats2half2_rn(c[nb][2] + bb.x, c[nb][3] + bb.y);
    }
    __syncthreads();

    // coalesced copy-out: 128 rows x 256B
    uint4* dst = (uint4*)(g_e + (size_t)e0 * HH);
    for (int i = tid; i < 2048; i += 256) {
        int r = i >> 4, ch = i & 15;
        dst[i] = *(const uint4*)((const char*)Ah + r * 272 + ch * 16);
    }
}

// -------- fused conv MLP: z = (relu(A@W1+b1))@W2+b2, + BN partial stats --------
// A = g_t (fp16); writes g_z (fp32, for pool) and g_hf (fp16, next layer input)
__global__ void __launch_bounds__(256) k_conv_tc(const __half* __restrict__ A,
                                                 const __half* __restrict__ w1h,
                                                 const __half* __restrict__ w2h,
                                                 const float* __restrict__ b1,
                                                 const float* __restrict__ b2,
                                                 float* __restrict__ Cc, int M) {
    extern __shared__ char smem[];
    __half* Ah = (__half*)smem;
    __half* Wh = Ah + 128 * SA;
    float* redS = (float*)(smem + 2 * 128 * SA * 2);   // [8][128]
    float* redQ = redS + 8 * 128;                      // [8][128]
    int tid = threadIdx.x, lane = tid & 31, wid = tid >> 5;
    int rowBase = blockIdx.x * 128;

    const uint4* A4 = (const uint4*)A;                 // 16 uint4 per row
    for (int idx = tid; idx < 128 * 16; idx += 256) {
        int r = idx >> 4, ch = idx & 15;
        int gr = rowBase + r;
        uint4 v = make_uint4(0u, 0u, 0u, 0u);
        if (gr < M) v = A4[(size_t)gr * 16 + ch];
        *(uint4*)((char*)Ah + r * 272 + ch * 16) = v;
    }
    copy_w(w1h, Wh, tid);
    __syncthreads();

    float c[16][4];
#pragma unroll
    for (int i = 0; i < 16; i++)
#pragma unroll
        for (int j = 0; j < 4; j++) c[i][j] = 0.f;
    gemm_fp16(Ah, Wh, c, wid * 16, lane);

    int g = lane >> 2, t2 = (lane & 3) * 2;
    int rb = wid * 16;
    // hidden = relu(c+b1) -> own rows of Ah
#pragma unroll
    for (int nb = 0; nb < 16; nb++) {
        int col = nb * 8 + t2;
        float2 bb = *(const float2*)(b1 + col);
        *(__half2*)(Ah + (rb + g) * SA + col) =
            __floats2half2_rn(fmaxf(c[nb][0] + bb.x, 0.f), fmaxf(c[nb][1] + bb.y, 0.f));
        *(__half2*)(Ah + (rb + g + 8) * SA + col) =
            __floats2half2_rn(fmaxf(c[nb][2] + bb.x, 0.f), fmaxf(c[nb][3] + bb.y, 0.f));
    }
    __syncthreads();
    copy_w(w2h, Wh, tid);
    __syncthreads();

#pragma unroll
    for (int i = 0; i < 16; i++)
#pragma unroll
        for (int j = 0; j < 4; j++) c[i][j] = 0.f;
    gemm_fp16(Ah, Wh, c, rb, lane);

    // epilogue: z -> g_z (fp32) + g_hf (fp16) + BN column partial sums
    int r0g = rowBase + rb + g, r1g = r0g + 8;
    bool v0 = r0g < M, v1 = r1g < M;
#pragma unroll
    for (int nb = 0; nb < 16; nb++) {
        int col = nb * 8 + t2;
        float2 bb = *(const float2*)(b2 + col);
        float z00 = c[nb][0] + bb.x, z01 = c[nb][1] + bb.y;
        float z10 = c[nb][2] + bb.x, z11 = c[nb][3] + bb.y;
        if (v0) {
            *(float2*)(Cc + (size_t)r0g * HH + col) = make_float2(z00, z01);
            *(__half2*)(g_hf + (size_t)r0g * HH + col) = __floats2half2_rn(z00, z01);
        }
        if (v1) {
            *(float2*)(Cc + (size_t)r1g * HH + col) = make_float2(z10, z11);
            *(__half2*)(g_hf + (size_t)r1g * HH + col) = __floats2half2_rn(z10, z11);
        }
        float s0 = (v0 ? z00 : 0.f) + (v1 ? z10 : 0.f);
        float s1 = (v0 ? z01 : 0.f) + (v1 ? z11 : 0.f);
        float q0 = (v0 ? z00 * z00 : 0.f) + (v1 ? z10 * z10 : 0.f);
        float q1 = (v0 ? z01 * z01 : 0.f) + (v1 ? z11 * z11 : 0.f);
#pragma unroll
        for (int m = 4; m <= 16; m <<= 1) {
            s0 += __shfl_xor_sync(0xffffffffu, s0, m);
            s1 += __shfl_xor_sync(0xffffffffu, s1, m);
            q0 += __shfl_xor_sync(0xffffffffu, q0, m);
            q1 += __shfl_xor_sync(0xffffffffu, q1, m);
        }
        if (lane < 4) {
            redS[wid * 128 + col] = s0;
            redS[wid * 128 + col + 1] = s1;
            redQ[wid * 128 + col] = q0;
            redQ[wid * 128 + col + 1] = q1;
        }
    }
    __syncthreads();
    if (tid < 128) {
        float s = 0.f;
#pragma unroll
        for (int w = 0; w < 8; w++) s += redS[w * 128 + tid];
        atomicAdd(&g_bnsum[tid], (double)s);
    } else {
        int col = tid - 128;
        float s = 0.f;
#pragma unroll
        for (int w = 0; w < 8; w++) s += redQ[w * 128 + col];
        atomicAdd(&g_bnsq[col], (double)s);
    }
}

// ---------------- node encoder: g_hf = fp16(x @ node_w + node_b) ----------------
__global__ void __launch_bounds__(128) k_node_enc(const float* __restrict__ x,
                                                  const float* __restrict__ w,
                                                  const float* __restrict__ b) {
    __shared__ float Xs[64 * NODE_IN];
    __shared__ float Wn[NODE_IN * HH];
    int tid = threadIdx.x;
    int rowBase = blockIdx.x * 64;
    const float4* W4 = (const float4*)w;
    float4* Wn4 = (float4*)Wn;
#pragma unroll
    for (int i = 0; i < 8; i++) Wn4[tid + 128 * i] = W4[tid + 128 * i];
    const float4* X4 = (const float4*)x;
    float4* Xs4 = (float4*)Xs;
#pragma unroll
    for (int i = 0; i < 4; i++) {
        int idx = tid + 128 * i;
        int r = idx >> 3;
        int gr = rowBase + r;
        float4 v = make_float4(0.f, 0.f, 0.f, 0.f);
        if (gr < NN) v = X4[(size_t)gr * 8 + (idx & 7)];
        Xs4[idx] = v;
    }
    __syncthreads();
    float wr[32];
#pragma unroll
    for (int k = 0; k < 32; k++) wr[k] = Wn[k * HH + tid];
    float bv = b[tid];
    for (int r = 0; r < 64; r++) {
        int gr = rowBase + r;
        if (gr >= NN) break;
        const float4* xr = (const float4*)(Xs + r * NODE_IN);
        float s = bv;
#pragma unroll
        for (int q = 0; q < 8; q++) {
            float4 xv = xr[q];
            s = fmaf(xv.x, wr[4 * q + 0], s);
            s = fmaf(xv.y, wr[4 * q + 1], s);
            s = fmaf(xv.z, wr[4 * q + 2], s);
            s = fmaf(xv.w, wr[4 * q + 3], s);
        }
        g_hf[(size_t)gr * HH + tid] = __float2half(s);
    }
}

// ---------------- CSR build ----------------
__global__ void k_zero() {
    int i = blockIdx.x * blockDim.x + threadIdx.x;
    if (i < NN) g_fill[i] = 0;
    if (i < GG * HH) g_pool[i] = 0.f;
    if (i < GG) g_cnt[i] = 0;
}
__global__ void k_degree(const int* __restrict__ dst) {
    int i = blockIdx.x * blockDim.x + threadIdx.x;
    if (i < EE) atomicAdd(&g_fill[dst[i]], 1);
}
__global__ void k_scan() {
    __shared__ int sdata[1024];
    __shared__ int carry;
    int tid = threadIdx.x;
    if (tid == 0) carry = 0;
    __syncthreads();
    for (int base = 0; base < NN; base += 1024) {
        int v = (base + tid < NN) ? g_fill[base + tid] : 0;
        sdata[tid] = v;
        __syncthreads();
        for (int off = 1; off < 1024; off <<= 1) {
            int t = (tid >= off) ? sdata[tid - off] : 0;
            __syncthreads();
            sdata[tid] += t;
            __syncthreads();
        }
        int cb = carry;
        if (base + tid < NN) {
            g_rowptr[base + tid] = cb + sdata[tid] - v;
            g_fill[base + tid] = 0;
        }
        __syncthreads();
        if (tid == 0) carry = cb + sdata[1023];
        __syncthreads();
    }
    if (tid == 0) g_rowptr[NN] = carry;
}
// fill CSR and permute edge_attr into slot order
__global__ void k_fillcsr(const int* __restrict__ ei, const float* __restrict__ ea) {
    int i = blockIdx.x * blockDim.x + threadIdx.x;
    if (i < EE) {
        int s = ei[i];
        int d = ei[EE + i];
        int p = atomicAdd(&g_fill[d], 1);
        int slot = g_rowptr[d] + p;
        g_src[slot] = s;
        const float4* src4 = (const float4*)(ea + (size_t)i * EDGE_IN);
        float4* dst4 = (float4*)(g_ea + (size_t)slot * EDGE_IN);
        dst4[0] = src4[0];
        dst4[1] = src4[1];
        dst4[2] = src4[2];
        dst4[3] = src4[3];
    }
}

// ---- aggregation: g_t = h_self + sum relu(h[src]+e); h = bn? relu(z*sc+sh) : z ----
__global__ void __launch_bounds__(256) k_aggregate(int bnflag) {
    int gw = (blockIdx.x * 256 + threadIdx.x) >> 5;
    int lane = threadIdx.x & 31;
    if (gw >= NN) return;
    float4 sc = make_float4(1.f, 1.f, 1.f, 1.f);
    float4 sh = make_float4(0.f, 0.f, 0.f, 0.f);
    if (bnflag) {
        sc = ((const float4*)g_bnscale)[lane];
        sh = ((const float4*)g_bnshift)[lane];
    }
    int beg = g_rowptr[gw], end = g_rowptr[gw + 1];
    const uint2* h2 = (const uint2*)g_hf;
    const uint2* e2 = (const uint2*)g_e;
    float4 acc = make_float4(0.f, 0.f, 0.f, 0.f);
    int j = beg;
    for (; j + 2 <= end; j += 2) {
        int s0 = g_src[j], s1 = g_src[j + 1];
        uint2 ew0 = e2[(size_t)j * 32 + lane];
        uint2 ew1 = e2[(size_t)(j + 1) * 32 + lane];
        uint2 hw0 = h2[(size_t)s0 * 32 + lane];
        uint2 hw1 = h2[(size_t)s1 * 32 + lane];
        float4 e0 = h4f(ew0), e1 = h4f(ew1);
        float4 h0 = h4f(hw0), h1 = h4f(hw1);
        h0.x = fmaf(h0.x, sc.x, sh.x); h0.y = fmaf(h0.y, sc.y, sh.y);
        h0.z = fmaf(h0.z, sc.z, sh.z); h0.w = fmaf(h0.w, sc.w, sh.w);
        h1.x = fmaf(h1.x, sc.x, sh.x); h1.y = fmaf(h1.y, sc.y, sh.y);
        h1.z = fmaf(h1.z, sc.z, sh.z); h1.w = fmaf(h1.w, sc.w, sh.w);
        if (bnflag) {
            h0.x = fmaxf(h0.x, 0.f); h0.y = fmaxf(h0.y, 0.f);
            h0.z = fmaxf(h0.z, 0.f); h0.w = fmaxf(h0.w, 0.f);
            h1.x = fmaxf(h1.x, 0.f); h1.y = fmaxf(h1.y, 0.f);
            h1.z = fmaxf(h1.z, 0.f); h1.w = fmaxf(h1.w, 0.f);
        }
        acc.x += fmaxf(h0.x + e0.x, 0.f) + fmaxf(h1.x + e1.x, 0.f);
        acc.y += fmaxf(h0.y + e0.y, 0.f) + fmaxf(h1.y + e1.y, 0.f);
        acc.z += fmaxf(h0.z + e0.z, 0.f) + fmaxf(h1.z + e1.z, 0.f);
        acc.w += fmaxf(h0.w + e0.w, 0.f) + fmaxf(h1.w + e1.w, 0.f);
    }
    if (j < end) {
        int s0 = g_src[j];
        float4 e0 = h4f(e2[(size_t)j * 32 + lane]);
        float4 h0 = h4f(h2[(size_t)s0 * 32 + lane]);
        h0.x = fmaf(h0.x, sc.x, sh.x); h0.y = fmaf(h0.y, sc.y, sh.y);
        h0.z = fmaf(h0.z, sc.z, sh.z); h0.w = fmaf(h0.w, sc.w, sh.w);
        if (bnflag) {
            h0.x = fmaxf(h0.x, 0.f); h0.y = fmaxf(h0.y, 0.f);
            h0.z = fmaxf(h0.z, 0.f); h0.w = fmaxf(h0.w, 0.f);
        }
        acc.x += fmaxf(h0.x + e0.x, 0.f);
        acc.y += fmaxf(h0.y + e0.y, 0.f);
        acc.z += fmaxf(h0.z + e0.z, 0.f);
        acc.w += fmaxf(h0.w + e0.w, 0.f);
    }
    float4 hs = h4f(h2[(size_t)gw * 32 + lane]);
    hs.x = fmaf(hs.x, sc.x, sh.x); hs.y = fmaf(hs.y, sc.y, sh.y);
    hs.z = fmaf(hs.z, sc.z, sh.z); hs.w = fmaf(hs.w, sc.w, sh.w);
    if (bnflag) {
        hs.x = fmaxf(hs.x, 0.f); hs.y = fmaxf(hs.y, 0.f);
        hs.z = fmaxf(hs.z, 0.f); hs.w = fmaxf(hs.w, 0.f);
    }
    acc.x += hs.x; acc.y += hs.y; acc.z += hs.z; acc.w += hs.w;
    ((uint2*)g_t)[(size_t)gw * 32 + lane] = f4h(acc);
}

// ---------------- batchnorm scalars ----------------
__global__ void k_bnzero() {
    int c = threadIdx.x;
    g_bnsum[c] = 0.0;
    g_bnsq[c] = 0.0;
}
__global__ void k_bnfinal(const float* __restrict__ gamma, const float* __restrict__ beta) {
    int c = threadIdx.x;
    double mean = g_bnsum[c] / (double)NN;
    double var = g_bnsq[c] / (double)NN - mean * mean;
    double inv = rsqrt(var + (double)BN_EPS);
    float sc = (float)((double)gamma[c] * inv);
    g_bnscale[c] = sc;
    g_bnshift[c] = (float)((double)beta[c] - mean * (double)sc);
}

// ---------------- pooling (applies final BN+relu on the fly, reads fp32 z) ----------------
__global__ void k_cnt(const int* __restrict__ batch) {
    int i = blockIdx.x * blockDim.x + threadIdx.x;
    if (i < NN) atomicAdd(&g_cnt[batch[i]], 1);
}
__global__ void __launch_bounds__(128) k_pool(const int* __restrict__ batch) {
    __shared__ int sb[256];
    int c = threadIdx.x;
    int r0 = blockIdx.x * 256;
    for (int i = c; i < 256; i += 128) {
        int r = r0 + i;
        sb[i] = (r < NN) ? batch[r] : -1;
    }
    __syncthreads();
    int rend = min(256, NN - r0);
    if (rend <= 0) return;
    float sc = g_bnscale[c], sh = g_bnshift[c];
    int cur = sb[0];
    float acc = 0.f;
    for (int i = 0; i < rend; i++) {
        int b = sb[i];
        if (b != cur) {
            atomicAdd(&g_pool[cur * HH + c], acc);
            acc = 0.f;
            cur = b;
        }
        acc += fmaxf(fmaf(g_z[(size_t)(r0 + i) * HH + c], sc, sh), 0.f);
    }
    atomicAdd(&g_pool[cur * HH + c], acc);
}

// ---------------- per-graph head ----------------
__global__ void __launch_bounds__(128) k_final(const float* __restrict__ ext,
                                               const float* __restrict__ ew1,
                                               const float* __restrict__ eb1,
                                               const float* __restrict__ ew2,
                                               const float* __restrict__ eb2,
                                               const float* __restrict__ rw1,
                                               const float* __restrict__ rb1,
                                               const float* __restrict__ rw2,
                                               const float* __restrict__ rb2,
                                               float* __restrict__ out) {
    int g = blockIdx.x, c = threadIdx.x;
    __shared__ float shid[HH];
    __shared__ float comb[2 * HH];
    __shared__ float red[HH];
    float xin[EXT_IN];
#pragma unroll
    for (int k = 0; k < EXT_IN; k++) xin[k] = ext[g * EXT_IN + k];
    float hval = eb1[c];
#pragma unroll
    for (int k = 0; k < EXT_IN; k++) hval = fmaf(xin[k], ew1[k * HH + c], hval);
    shid[c] = fmaxf(hval, 0.f);
    __syncthreads();
    float eo = eb2[c];
    for (int k = 0; k < HH; k++) eo = fmaf(shid[k], ew2[k * HH + c], eo);
    float cnt = fmaxf((float)g_cnt[g], 1.f);
    comb[c] = g_pool[g * HH + c] / cnt;
    comb[HH + c] = eo;
    __syncthreads();
    float rh = rb1[c];
    for (int k = 0; k < 2 * HH; k++) rh = fmaf(comb[k], rw1[k * HH + c], rh);
    rh = fmaxf(rh, 0.f);
    red[c] = rh * rw2[c];
    __syncthreads();
    for (int s = 64; s > 0; s >>= 1) {
        if (c < s) red[c] += red[c + s];
        __syncthreads();
    }
    if (c == 0) out[g] = red[0] + rb2[0];
}

// ---------------- host launcher ----------------
extern "C" void kernel_launch(void* const* d_in, const int* in_sizes, int n_in,
                              void* d_out, int out_size) {
    const float* x         = (const float*)d_in[0];
    const float* edge_attr = (const float*)d_in[1];
    const float* externals = (const float*)d_in[2];
    const float* node_w    = (const float*)d_in[3];
    const float* node_b    = (const float*)d_in[4];
    const float* ee_w1     = (const float*)d_in[5];
    const float* ee_b1     = (const float*)d_in[6];
    const float* ee_w2     = (const float*)d_in[7];
    const float* ee_b2     = (const float*)d_in[8];
    const float* conv_w1   = (const float*)d_in[9];
    const float* conv_b1   = (const float*)d_in[10];
    const float* conv_w2   = (const float*)d_in[11];
    const float* conv_b2   = (const float*)d_in[12];
    const float* bn_gamma  = (const float*)d_in[13];
    const float* bn_beta   = (const float*)d_in[14];
    const float* ext_w1    = (const float*)d_in[15];
    const float* ext_b1    = (const float*)d_in[16];
    const float* ext_w2    = (const float*)d_in[17];
    const float* ext_b2    = (const float*)d_in[18];
    const float* reg_w1    = (const float*)d_in[19];
    const float* reg_b1    = (const float*)d_in[20];
    const float* reg_w2    = (const float*)d_in[21];
    const float* reg_b2    = (const float*)d_in[22];
    const int* edge_index  = (const int*)d_in[23];
    const int* batch       = (const int*)d_in[24];
    float* out = (float*)d_out;

    static bool attr_done = false;
    if (!attr_done) {
        cudaFuncSetAttribute(k_edge_tc, cudaFuncAttributeMaxDynamicSharedMemorySize, SMEM_BIG);
        cudaFuncSetAttribute(k_conv_tc, cudaFuncAttributeMaxDynamicSharedMemorySize, SMEM_BIG);
        attr_done = true;
    }

    float* p_z;
    cudaGetSymbolAddress((void**)&p_z, g_z);
    __half *p_wh, *p_t;
    cudaGetSymbolAddress((void**)&p_wh, g_wh);
    cudaGetSymbolAddress((void**)&p_t, g_t);

    // launch order front-loads CSR deps so ncu (-s 5 -c 1) captures k_edge_tc (launch #6)
    k_wprep<<<dim3(64, 7), 256>>>(ee_w2, conv_w1, conv_w2);          // 1
    k_zero<<<(NN + 255) / 256, 256>>>();                             // 2
    k_degree<<<(EE + 255) / 256, 256>>>(edge_index + EE);            // 3
    k_scan<<<1, 1024>>>();                                           // 4
    k_fillcsr<<<(EE + 255) / 256, 256>>>(edge_index, edge_attr);     // 5
    k_edge_tc<<<EE / 128, 256, SMEM_BIG>>>(ee_w1, ee_b1, p_wh, ee_b2); // 6 <- profiled
    k_node_enc<<<(NN + 63) / 64, 128>>>(x, node_w, node_b);          // 7

    // 3x (aggregate [+prev BN fused] -> fused conv MLP [+BN stats] -> BN scalars)
    for (int l = 0; l < 3; l++) {
        k_bnzero<<<1, 128>>>();
        k_aggregate<<<(NN * 32 + 255) / 256, 256>>>(l > 0 ? 1 : 0);
        k_conv_tc<<<(NN + 127) / 128, 256, SMEM_BIG>>>(
            p_t,
            p_wh + (size_t)(1 + l) * HH * HH,
            p_wh + (size_t)(4 + l) * HH * HH,
            conv_b1 + (size_t)l * HH, conv_b2 + (size_t)l * HH, p_z, NN);
        k_bnfinal<<<1, 128>>>(bn_gamma + (size_t)l * HH, bn_beta + (size_t)l * HH);
    }

    // pooling (applies layer-3 BN+relu) + head
    k_cnt<<<(NN + 255) / 256, 256>>>(batch);
    k_pool<<<(NN + 255) / 256, 128>>>(batch);
    k_final<<<GG, 128>>>(externals, ext_w1, ext_b1, ext_w2, ext_b2,
                         reg_w1, reg_b1, reg_w2, reg_b2, out);
}